// round 1
// baseline (speedup 1.0000x reference)
#include <cuda_runtime.h>
#include <cstddef>

// Problem constants
#define BB 2
#define TT 2048
#define DD 2048
#define HH 16
#define GG 4
#define DK 128
#define RF (HH / GG)   // 4

// Scratch (no cudaMalloc allowed)
__device__ float g_q[(size_t)BB * TT * HH * DK]; // 8M floats
__device__ float g_k[(size_t)BB * TT * GG * DK]; // 2M
__device__ float g_v[(size_t)BB * TT * GG * DK]; // 2M
__device__ float g_y[(size_t)BB * TT * DD];      // 8M

// ---------------------------------------------------------------------------
// SGEMM: C[M,N] = A[M,K] @ B[K,N], all row-major fp32.
// Tiles: BM=BN=64, BK=16, 256 threads, 4x4 microtile. Requires M%64==0,
// N%64==0, K%16==0 (true for all shapes here).
// ---------------------------------------------------------------------------
__global__ __launch_bounds__(256) void sgemm64(const float* __restrict__ A,
                                               const float* __restrict__ B,
                                               float* __restrict__ C,
                                               int M, int N, int K) {
    __shared__ float As[64][16];
    __shared__ float Bs[16][68];  // pad to 68 for conflict-free float4 reads

    const int n0 = blockIdx.x * 64;
    const int m0 = blockIdx.y * 64;
    const int tid = threadIdx.x;
    const int tx = tid & 15;       // 0..15 -> N
    const int ty = tid >> 4;       // 0..15 -> M

    float acc[4][4];
#pragma unroll
    for (int i = 0; i < 4; i++)
#pragma unroll
        for (int j = 0; j < 4; j++) acc[i][j] = 0.f;

    const int arow = tid >> 2, ac4 = tid & 3;   // A: 64 rows x 4 float4
    const int brow = tid >> 4, bc4 = tid & 15;  // B: 16 rows x 16 float4

    for (int k0 = 0; k0 < K; k0 += 16) {
        float4 av = *(const float4*)(A + (size_t)(m0 + arow) * K + k0 + ac4 * 4);
        *(float4*)(&As[arow][ac4 * 4]) = av;
        float4 bv = *(const float4*)(B + (size_t)(k0 + brow) * N + n0 + bc4 * 4);
        *(float4*)(&Bs[brow][bc4 * 4]) = bv;
        __syncthreads();

#pragma unroll
        for (int kk = 0; kk < 16; kk++) {
            float a0 = As[ty * 4 + 0][kk];
            float a1 = As[ty * 4 + 1][kk];
            float a2 = As[ty * 4 + 2][kk];
            float a3 = As[ty * 4 + 3][kk];
            float4 b4 = *(const float4*)(&Bs[kk][tx * 4]);
            acc[0][0] += a0 * b4.x; acc[0][1] += a0 * b4.y; acc[0][2] += a0 * b4.z; acc[0][3] += a0 * b4.w;
            acc[1][0] += a1 * b4.x; acc[1][1] += a1 * b4.y; acc[1][2] += a1 * b4.z; acc[1][3] += a1 * b4.w;
            acc[2][0] += a2 * b4.x; acc[2][1] += a2 * b4.y; acc[2][2] += a2 * b4.z; acc[2][3] += a2 * b4.w;
            acc[3][0] += a3 * b4.x; acc[3][1] += a3 * b4.y; acc[3][2] += a3 * b4.z; acc[3][3] += a3 * b4.w;
        }
        __syncthreads();
    }

#pragma unroll
    for (int i = 0; i < 4; i++) {
        float4 cv = make_float4(acc[i][0], acc[i][1], acc[i][2], acc[i][3]);
        *(float4*)(C + (size_t)(m0 + ty * 4 + i) * N + n0 + tx * 4) = cv;
    }
}

// ---------------------------------------------------------------------------
// RoPE in place on a (B, T, nh, 128) fp32 tensor.
// inv_freq[i] = 10000^(-i/64), i in [0,64)
// ---------------------------------------------------------------------------
__global__ void rope_kernel(float* __restrict__ p, int nh, int total) {
    int idx = blockIdx.x * blockDim.x + threadIdx.x;
    if (idx >= total) return;
    int i  = idx & 63;
    int h  = (idx >> 6) % nh;
    int bt = idx / (64 * nh);
    int t  = bt % TT;

    const float log_theta_over_64 = 0.14391156f; // ln(10000)/64
    float freq = __expf(-(float)i * log_theta_over_64);
    float ang  = (float)t * freq;
    float s, c;
    sincosf(ang, &s, &c);

    size_t base = ((size_t)bt * nh + h) * DK;
    float x1 = p[base + i];
    float x2 = p[base + 64 + i];
    p[base + i]      = x1 * c - x2 * s;
    p[base + 64 + i] = x2 * c + x1 * s;
}

// ---------------------------------------------------------------------------
// Flash-attention (causal, GQA). One CTA = 64 query rows of one (b,h).
// Online softmax, fp32 throughout. 256 threads.
// O microtile: thread (ty,tx) owns rows ty*4..+3, cols tx*8..+7.
// ---------------------------------------------------------------------------
#define KS_PAD 129
#define SS_PAD 65
#define ATT_SMEM ((64 * 128 + 64 * KS_PAD + 64 * 128 + 64 * SS_PAD + 3 * 64) * 4)

__global__ __launch_bounds__(256) void attn_kernel(const float* __restrict__ q,
                                                   const float* __restrict__ k,
                                                   const float* __restrict__ v,
                                                   float* __restrict__ y) {
    const int qt = blockIdx.x;          // query tile
    const int h  = blockIdx.y;          // head
    const int b  = blockIdx.z;          // batch
    const int q0 = qt * 64;
    const int g  = h / RF;              // kv head

    const int tid = threadIdx.x;
    const int tx  = tid & 15;
    const int ty  = tid >> 4;

    extern __shared__ float sm[];
    float* Qs   = sm;                         // [64][128]
    float* Ks   = Qs + 64 * 128;              // [64][129]
    float* Vs   = Ks + 64 * KS_PAD;           // [64][128]
    float* Ss   = Vs + 64 * 128;              // [64][65]
    float* mrow = Ss + 64 * SS_PAD;           // [64]
    float* lrow = mrow + 64;                  // [64]
    float* arow = lrow + 64;                  // [64]

    // Load Q tile (already RoPE'd), float4
    for (int it = tid; it < 64 * 32; it += 256) {
        int row = it >> 5, c4 = it & 31;
        const float4* src = (const float4*)(q + (((size_t)(b * TT + q0 + row)) * HH + h) * DK);
        ((float4*)(Qs + row * 128))[c4] = src[c4];
    }
    if (tid < 64) { mrow[tid] = -1e30f; lrow[tid] = 0.f; }

    float acc[4][8];
#pragma unroll
    for (int i = 0; i < 4; i++)
#pragma unroll
        for (int j = 0; j < 8; j++) acc[i][j] = 0.f;

    __syncthreads();

    const float rs = 0.08838834764831845f; // 1/sqrt(128)
    const int ktiles = qt + 1;              // causal

    for (int kt = 0; kt < ktiles; kt++) {
        const int k0 = kt * 64;

        // Load K (scalar, padded) and V (float4)
        for (int it = tid; it < 64 * 128; it += 256) {
            int row = it >> 7, col = it & 127;
            Ks[row * KS_PAD + col] =
                k[(((size_t)(b * TT + k0 + row)) * GG + g) * DK + col];
        }
        for (int it = tid; it < 64 * 32; it += 256) {
            int row = it >> 5, c4 = it & 31;
            const float4* src = (const float4*)(v + (((size_t)(b * TT + k0 + row)) * GG + g) * DK);
            ((float4*)(Vs + row * 128))[c4] = src[c4];
        }
        __syncthreads();

        // Phase 1: S = Q K^T (4x4 microtile over 64x64)
        float s4[4][4];
#pragma unroll
        for (int i = 0; i < 4; i++)
#pragma unroll
            for (int j = 0; j < 4; j++) s4[i][j] = 0.f;

#pragma unroll 8
        for (int d = 0; d < 128; d++) {
            float qreg[4], kreg[4];
#pragma unroll
            for (int i = 0; i < 4; i++) qreg[i] = Qs[(ty * 4 + i) * 128 + d];
#pragma unroll
            for (int j = 0; j < 4; j++) kreg[j] = Ks[(tx * 4 + j) * KS_PAD + d];
#pragma unroll
            for (int i = 0; i < 4; i++)
#pragma unroll
                for (int j = 0; j < 4; j++) s4[i][j] += qreg[i] * kreg[j];
        }

        // Scale + causal mask -> Ss
        const bool diag = (kt == qt);
#pragma unroll
        for (int i = 0; i < 4; i++) {
            int row = ty * 4 + i;
#pragma unroll
            for (int j = 0; j < 4; j++) {
                int col = tx * 4 + j;
                float sv = s4[i][j] * rs;
                if (diag && (k0 + col > q0 + row)) sv = -1e30f;
                Ss[row * SS_PAD + col] = sv;
            }
        }
        __syncthreads();

        // Online softmax per row (64 threads)
        if (tid < 64) {
            float mo = mrow[tid];
            float mx = mo;
#pragma unroll 8
            for (int j = 0; j < 64; j++) mx = fmaxf(mx, Ss[tid * SS_PAD + j]);
            float al = expf(mo - mx);
            float sum = 0.f;
#pragma unroll 4
            for (int j = 0; j < 64; j++) {
                float pv = expf(Ss[tid * SS_PAD + j] - mx);
                Ss[tid * SS_PAD + j] = pv;
                sum += pv;
            }
            lrow[tid] = lrow[tid] * al + sum;
            mrow[tid] = mx;
            arow[tid] = al;
        }
        __syncthreads();

        // Rescale O accumulators
#pragma unroll
        for (int i = 0; i < 4; i++) {
            float al = arow[ty * 4 + i];
#pragma unroll
            for (int j = 0; j < 8; j++) acc[i][j] *= al;
        }

        // Phase 2: O += P @ V
#pragma unroll 4
        for (int kk = 0; kk < 64; kk++) {
            float preg[4];
#pragma unroll
            for (int i = 0; i < 4; i++) preg[i] = Ss[(ty * 4 + i) * SS_PAD + kk];
            float4 v0 = *(const float4*)(Vs + kk * 128 + tx * 8);
            float4 v1 = *(const float4*)(Vs + kk * 128 + tx * 8 + 4);
#pragma unroll
            for (int i = 0; i < 4; i++) {
                acc[i][0] += preg[i] * v0.x;
                acc[i][1] += preg[i] * v0.y;
                acc[i][2] += preg[i] * v0.z;
                acc[i][3] += preg[i] * v0.w;
                acc[i][4] += preg[i] * v1.x;
                acc[i][5] += preg[i] * v1.y;
                acc[i][6] += preg[i] * v1.z;
                acc[i][7] += preg[i] * v1.w;
            }
        }
        __syncthreads();  // protect Ks/Vs/Ss/arow for next iter
    }

    // Epilogue: normalize and write y in (b,t,h,dk) = (b,t,D) layout
#pragma unroll
    for (int i = 0; i < 4; i++) {
        int row = ty * 4 + i;
        float inv = 1.f / lrow[row];
        size_t base = ((size_t)(b * TT + q0 + row)) * DD + h * DK + tx * 8;
#pragma unroll
        for (int j = 0; j < 8; j++) y[base + j] = acc[i][j] * inv;
    }
}

// ---------------------------------------------------------------------------
// Launch
// ---------------------------------------------------------------------------
extern "C" void kernel_launch(void* const* d_in, const int* in_sizes, int n_in,
                              void* d_out, int out_size) {
    const float* x  = (const float*)d_in[0];
    const float* Wq = (const float*)d_in[1];
    const float* Wk = (const float*)d_in[2];
    const float* Wv = (const float*)d_in[3];
    const float* Wo = (const float*)d_in[4];
    // d_in[5] = mask (causal tril, recomputed), d_in[6] = pos (arange, recomputed)
    float* out = (float*)d_out;

    float *q, *k, *v, *y;
    cudaGetSymbolAddress((void**)&q, g_q);
    cudaGetSymbolAddress((void**)&k, g_k);
    cudaGetSymbolAddress((void**)&v, g_v);
    cudaGetSymbolAddress((void**)&y, g_y);

    const int M = BB * TT;  // 4096

    // QKV projections
    sgemm64<<<dim3(DD / 64, M / 64), 256>>>(x, Wq, q, M, HH * DK, DD);
    sgemm64<<<dim3((GG * DK) / 64, M / 64), 256>>>(x, Wk, k, M, GG * DK, DD);
    sgemm64<<<dim3((GG * DK) / 64, M / 64), 256>>>(x, Wv, v, M, GG * DK, DD);

    // RoPE
    {
        int tq = BB * TT * HH * 64;
        int tk = BB * TT * GG * 64;
        rope_kernel<<<(tq + 255) / 256, 256>>>(q, HH, tq);
        rope_kernel<<<(tk + 255) / 256, 256>>>(k, GG, tk);
    }

    // Attention
    cudaFuncSetAttribute(attn_kernel, cudaFuncAttributeMaxDynamicSharedMemorySize,
                         ATT_SMEM);
    attn_kernel<<<dim3(TT / 64, HH, BB), 256, ATT_SMEM>>>(q, k, v, y);

    // Output projection
    sgemm64<<<dim3(DD / 64, M / 64), 256>>>(y, Wo, out, M, DD, DD);
}

// round 2
// speedup vs baseline: 1.4753x; 1.4753x over previous
#include <cuda_runtime.h>
#include <mma.h>
#include <cstddef>

using namespace nvcuda;

// Problem constants
#define BB 2
#define TT 2048
#define DD 2048
#define HH 16
#define GG 4
#define DK 128
#define RF (HH / GG)   // 4

// Scratch (no cudaMalloc allowed)
__device__ float g_q[(size_t)BB * TT * HH * DK];
__device__ float g_k[(size_t)BB * TT * GG * DK];
__device__ float g_v[(size_t)BB * TT * GG * DK];
__device__ float g_y[(size_t)BB * TT * DD];

__device__ __forceinline__ float to_tf32(float x) {
    return wmma::__float_to_tf32(x);
}
__device__ __forceinline__ float4 tf32x4(float4 v) {
    v.x = to_tf32(v.x); v.y = to_tf32(v.y);
    v.z = to_tf32(v.z); v.w = to_tf32(v.w);
    return v;
}

// ---------------------------------------------------------------------------
// TF32 tensor-core GEMM: C[M,N] = A[M,K] @ B[K,N], row-major fp32 in/out.
// CTA tile 128x128, BK=16, 256 threads (8 warps, each 64x32).
// Requires M%128==0, N%128==0, K%16==0.
// ---------------------------------------------------------------------------
#define ALD 24
#define BLD 132

__global__ __launch_bounds__(256) void sgemm_tc(const float* __restrict__ A,
                                                const float* __restrict__ B,
                                                float* __restrict__ C,
                                                int M, int N, int K) {
    __shared__ __align__(16) float As[128 * ALD];
    __shared__ __align__(16) float Bs[16 * BLD];

    const int tid  = threadIdx.x;
    const int warp = tid >> 5;
    const int wm   = (warp & 1) * 64;   // warp m offset within CTA tile
    const int wn   = (warp >> 1) * 32;  // warp n offset
    const int m0   = blockIdx.y * 128;
    const int n0   = blockIdx.x * 128;

    // load maps
    const int aRow = tid >> 2;            // 0..63 (second item +64)
    const int aC4  = (tid & 3) * 4;       // float offset
    const int bRow = tid >> 5;            // 0..7 (second item +8)
    const int bC4  = (tid & 31) * 4;

    wmma::fragment<wmma::accumulator, 16, 16, 8, float> acc[4][2];
#pragma unroll
    for (int i = 0; i < 4; i++)
#pragma unroll
        for (int j = 0; j < 2; j++) wmma::fill_fragment(acc[i][j], 0.f);

    const float* Ap = A + (size_t)m0 * K;
    const float* Bp = B + n0;

    float4 ra0, ra1, rb0, rb1;

    // fetch tile k0 into regs
    auto fetch = [&](int k0) {
        ra0 = *(const float4*)(Ap + (size_t)aRow * K + k0 + aC4);
        ra1 = *(const float4*)(Ap + (size_t)(aRow + 64) * K + k0 + aC4);
        rb0 = *(const float4*)(Bp + (size_t)(k0 + bRow) * N + bC4);
        rb1 = *(const float4*)(Bp + (size_t)(k0 + bRow + 8) * N + bC4);
    };
    auto stsm = [&]() {
        *(float4*)(As + aRow * ALD + aC4)        = tf32x4(ra0);
        *(float4*)(As + (aRow + 64) * ALD + aC4) = tf32x4(ra1);
        *(float4*)(Bs + bRow * BLD + bC4)        = tf32x4(rb0);
        *(float4*)(Bs + (bRow + 8) * BLD + bC4)  = tf32x4(rb1);
    };

    fetch(0);
    stsm();
    __syncthreads();

    for (int k0 = 0; k0 < K; k0 += 16) {
        const bool has_next = (k0 + 16) < K;
        if (has_next) fetch(k0 + 16);

#pragma unroll
        for (int ks = 0; ks < 16; ks += 8) {
            wmma::fragment<wmma::matrix_a, 16, 16, 8, wmma::precision::tf32,
                           wmma::row_major> af[4];
            wmma::fragment<wmma::matrix_b, 16, 16, 8, wmma::precision::tf32,
                           wmma::row_major> bf[2];
#pragma unroll
            for (int i = 0; i < 4; i++)
                wmma::load_matrix_sync(af[i], As + (wm + i * 16) * ALD + ks, ALD);
#pragma unroll
            for (int j = 0; j < 2; j++)
                wmma::load_matrix_sync(bf[j], Bs + ks * BLD + wn + j * 16, BLD);
#pragma unroll
            for (int i = 0; i < 4; i++)
#pragma unroll
                for (int j = 0; j < 2; j++)
                    wmma::mma_sync(acc[i][j], af[i], bf[j], acc[i][j]);
        }

        if (has_next) {
            __syncthreads();
            stsm();
            __syncthreads();
        }
    }

#pragma unroll
    for (int i = 0; i < 4; i++)
#pragma unroll
        for (int j = 0; j < 2; j++)
            wmma::store_matrix_sync(C + (size_t)(m0 + wm + i * 16) * N +
                                        n0 + wn + j * 16,
                                    acc[i][j], N, wmma::mem_row_major);
}

// ---------------------------------------------------------------------------
// RoPE in place on a (B, T, nh, 128) fp32 tensor.
// ---------------------------------------------------------------------------
__global__ void rope_kernel(float* __restrict__ p, int nh, int total) {
    int idx = blockIdx.x * blockDim.x + threadIdx.x;
    if (idx >= total) return;
    int i  = idx & 63;
    int h  = (idx >> 6) % nh;
    int bt = idx / (64 * nh);
    int t  = bt % TT;

    const float log_theta_over_64 = 0.14391156f; // ln(10000)/64
    float freq = __expf(-(float)i * log_theta_over_64);
    float ang  = (float)t * freq;
    float s, c;
    sincosf(ang, &s, &c);

    size_t base = ((size_t)bt * nh + h) * DK;
    float x1 = p[base + i];
    float x2 = p[base + 64 + i];
    p[base + i]      = x1 * c - x2 * s;
    p[base + 64 + i] = x2 * c + x1 * s;
}

// ---------------------------------------------------------------------------
// Flash attention (causal, GQA) with TF32 wmma for QK^T and PV.
// One CTA = 64 query rows of one (b,h). 256 threads = 8 warps.
// O accumulator lives in smem (fp32) so per-row online-softmax rescale is exact.
// ---------------------------------------------------------------------------
#define QLD 132
#define KLD 68
#define VLD 132
#define SLD 68
#define OLD 132
// floats: Qs 64*132 + Kst 128*68 + Vs 64*132 + Ss 64*68 + Os 64*132 + 192
#define ATT_SMEM ((64 * QLD + 128 * KLD + 64 * VLD + 64 * SLD + 64 * OLD + 192) * 4)

__global__ __launch_bounds__(256) void attn_tc(const float* __restrict__ q,
                                               const float* __restrict__ k,
                                               const float* __restrict__ v,
                                               float* __restrict__ y) {
    const int qt = blockIdx.x;
    const int h  = blockIdx.y;
    const int b  = blockIdx.z;
    const int q0 = qt * 64;
    const int g  = h / RF;

    const int tid  = threadIdx.x;
    const int warp = tid >> 5;

    extern __shared__ __align__(16) float sm[];
    float* Qs   = sm;                     // [64][QLD]  (q rows x d)
    float* Kst  = Qs  + 64 * QLD;         // [128][KLD] (d x keys, transposed)
    float* Vs   = Kst + 128 * KLD;        // [64][VLD]  (keys x d)
    float* Ss   = Vs  + 64 * VLD;         // [64][SLD]  (S then P)
    float* Os   = Ss  + 64 * SLD;         // [64][OLD]  (O accumulator, fp32)
    float* mrow = Os  + 64 * OLD;
    float* lrow = mrow + 64;
    float* arow = lrow + 64;

    // Load Q tile (rounded to tf32); zero O.
    for (int it = tid; it < 64 * 32; it += 256) {
        int row = it >> 5, c4 = (it & 31) * 4;
        float4 val = *(const float4*)(q + (((size_t)(b * TT + q0 + row)) * HH + h) * DK + c4);
        *(float4*)(Qs + row * QLD + c4) = tf32x4(val);
        *(float4*)(Os + row * OLD + c4) = make_float4(0.f, 0.f, 0.f, 0.f);
    }
    if (tid < 64) { mrow[tid] = -1e30f; lrow[tid] = 0.f; }
    __syncthreads();

    const float rs = 0.08838834764831845f; // 1/sqrt(128)

    for (int kt = 0; kt <= qt; kt++) {
        const int k0 = kt * 64;

        // Load K transposed (d-major) and V (key-major), tf32-rounded.
        for (int it = tid; it < 64 * 32; it += 256) {
            int key = it >> 5, c4 = (it & 31) * 4;
            float4 kv = *(const float4*)(k + (((size_t)(b * TT + k0 + key)) * GG + g) * DK + c4);
            Kst[(c4 + 0) * KLD + key] = to_tf32(kv.x);
            Kst[(c4 + 1) * KLD + key] = to_tf32(kv.y);
            Kst[(c4 + 2) * KLD + key] = to_tf32(kv.z);
            Kst[(c4 + 3) * KLD + key] = to_tf32(kv.w);
            float4 vv = *(const float4*)(v + (((size_t)(b * TT + k0 + key)) * GG + g) * DK + c4);
            *(float4*)(Vs + key * VLD + c4) = tf32x4(vv);
        }
        __syncthreads();

        // Phase 1: S = Q K^T. 4x4 grid of 16x16 tiles; warp w -> m tile w&3,
        // n tiles {(w>>2)*2, +1}.
        {
            const int mt = (warp & 3) * 16;
            const int nb = (warp >> 2) * 32;
            wmma::fragment<wmma::accumulator, 16, 16, 8, float> sa[2];
            wmma::fill_fragment(sa[0], 0.f);
            wmma::fill_fragment(sa[1], 0.f);
#pragma unroll
            for (int kk = 0; kk < 128; kk += 8) {
                wmma::fragment<wmma::matrix_a, 16, 16, 8, wmma::precision::tf32,
                               wmma::row_major> af;
                wmma::load_matrix_sync(af, Qs + mt * QLD + kk, QLD);
#pragma unroll
                for (int j = 0; j < 2; j++) {
                    wmma::fragment<wmma::matrix_b, 16, 16, 8, wmma::precision::tf32,
                                   wmma::row_major> bf;
                    wmma::load_matrix_sync(bf, Kst + kk * KLD + nb + j * 16, KLD);
                    wmma::mma_sync(sa[j], af, bf, sa[j]);
                }
            }
            wmma::store_matrix_sync(Ss + mt * SLD + nb,      sa[0], SLD, wmma::mem_row_major);
            wmma::store_matrix_sync(Ss + mt * SLD + nb + 16, sa[1], SLD, wmma::mem_row_major);
        }
        __syncthreads();

        // Online softmax: 4 threads per row, 16 cols each.
        {
            const int r  = tid >> 2;
            const int qd = tid & 3;
            float mo = mrow[r];
            float sv[16];
            float mx = mo;
#pragma unroll
            for (int j = 0; j < 16; j++) {
                int c = qd * 16 + j;
                float s = Ss[r * SLD + c] * rs;
                if (k0 + c > q0 + r) s = -1e30f;  // causal
                sv[j] = s;
                mx = fmaxf(mx, s);
            }
            mx = fmaxf(mx, __shfl_xor_sync(0xffffffffu, mx, 1));
            mx = fmaxf(mx, __shfl_xor_sync(0xffffffffu, mx, 2));
            float sum = 0.f;
#pragma unroll
            for (int j = 0; j < 16; j++) {
                float p = __expf(sv[j] - mx);
                Ss[r * SLD + qd * 16 + j] = p;
                sum += p;
            }
            sum += __shfl_xor_sync(0xffffffffu, sum, 1);
            sum += __shfl_xor_sync(0xffffffffu, sum, 2);
            if (qd == 0) {
                float al = __expf(mo - mx);
                lrow[r] = lrow[r] * al + sum;
                mrow[r] = mx;
                arow[r] = al;
            }
        }
        __syncthreads();

        // Rescale O accumulator rows.
        for (int it = tid; it < 64 * 32; it += 256) {
            int row = it >> 5, c4 = (it & 31) * 4;
            float al = arow[row];
            float4* p = (float4*)(Os + row * OLD + c4);
            float4 o = *p;
            o.x *= al; o.y *= al; o.z *= al; o.w *= al;
            *p = o;
        }
        __syncthreads();

        // Phase 2: O += P @ V. 4x8 grid of 16x16 tiles; warp w -> m tile w&3,
        // n tiles (w>>2)*4 .. +3.
        {
            const int mt = (warp & 3) * 16;
            const int nb = (warp >> 2) * 64;
            wmma::fragment<wmma::accumulator, 16, 16, 8, float> oa[4];
#pragma unroll
            for (int j = 0; j < 4; j++)
                wmma::load_matrix_sync(oa[j], Os + mt * OLD + nb + j * 16, OLD,
                                       wmma::mem_row_major);
#pragma unroll
            for (int kk = 0; kk < 64; kk += 8) {
                wmma::fragment<wmma::matrix_a, 16, 16, 8, wmma::precision::tf32,
                               wmma::row_major> af;
                wmma::load_matrix_sync(af, Ss + mt * SLD + kk, SLD);
#pragma unroll
                for (int j = 0; j < 4; j++) {
                    wmma::fragment<wmma::matrix_b, 16, 16, 8, wmma::precision::tf32,
                                   wmma::row_major> bf;
                    wmma::load_matrix_sync(bf, Vs + kk * VLD + nb + j * 16, VLD);
                    wmma::mma_sync(oa[j], af, bf, oa[j]);
                }
            }
#pragma unroll
            for (int j = 0; j < 4; j++)
                wmma::store_matrix_sync(Os + mt * OLD + nb + j * 16, oa[j], OLD,
                                        wmma::mem_row_major);
        }
        __syncthreads();
    }

    // Epilogue: normalize and write y in (b,t,D) layout.
    for (int it = tid; it < 64 * 32; it += 256) {
        int row = it >> 5, c4 = (it & 31) * 4;
        float inv = 1.f / lrow[row];
        float4 o = *(const float4*)(Os + row * OLD + c4);
        o.x *= inv; o.y *= inv; o.z *= inv; o.w *= inv;
        *(float4*)(y + ((size_t)(b * TT + q0 + row)) * DD + h * DK + c4) = o;
    }
}

// ---------------------------------------------------------------------------
// Launch
// ---------------------------------------------------------------------------
extern "C" void kernel_launch(void* const* d_in, const int* in_sizes, int n_in,
                              void* d_out, int out_size) {
    const float* x  = (const float*)d_in[0];
    const float* Wq = (const float*)d_in[1];
    const float* Wk = (const float*)d_in[2];
    const float* Wv = (const float*)d_in[3];
    const float* Wo = (const float*)d_in[4];
    float* out = (float*)d_out;

    float *q, *k, *v, *y;
    cudaGetSymbolAddress((void**)&q, g_q);
    cudaGetSymbolAddress((void**)&k, g_k);
    cudaGetSymbolAddress((void**)&v, g_v);
    cudaGetSymbolAddress((void**)&y, g_y);

    const int M = BB * TT;  // 4096

    // QKV projections (tf32 tensor cores)
    sgemm_tc<<<dim3(DD / 128, M / 128), 256>>>(x, Wq, q, M, HH * DK, DD);
    sgemm_tc<<<dim3((GG * DK) / 128, M / 128), 256>>>(x, Wk, k, M, GG * DK, DD);
    sgemm_tc<<<dim3((GG * DK) / 128, M / 128), 256>>>(x, Wv, v, M, GG * DK, DD);

    // RoPE
    {
        int tq = BB * TT * HH * 64;
        int tk = BB * TT * GG * 64;
        rope_kernel<<<(tq + 255) / 256, 256>>>(q, HH, tq);
        rope_kernel<<<(tk + 255) / 256, 256>>>(k, GG, tk);
    }

    // Attention
    cudaFuncSetAttribute(attn_tc, cudaFuncAttributeMaxDynamicSharedMemorySize,
                         ATT_SMEM);
    attn_tc<<<dim3(TT / 64, HH, BB), 256, ATT_SMEM>>>(q, k, v, y);

    // Output projection
    sgemm_tc<<<dim3(DD / 128, M / 128), 256>>>(y, Wo, out, M, DD, DD);
}

// round 4
// speedup vs baseline: 1.7589x; 1.1922x over previous
#include <cuda_runtime.h>
#include <cuda_bf16.h>
#include <mma.h>
#include <cstdint>
#include <cstddef>

using namespace nvcuda;

// Problem constants
#define BB 2
#define TT 2048
#define DD 2048
#define HH 16
#define GG 4
#define DK 128
#define RF (HH / GG)   // 4

// ---------------------------------------------------------------------------
// Scratch (__device__ globals; no allocation allowed)
// ---------------------------------------------------------------------------
__device__ __align__(16) float g_q[(size_t)BB * TT * HH * DK];
__device__ __align__(16) float g_k[(size_t)BB * TT * GG * DK];
__device__ __align__(16) float g_v[(size_t)BB * TT * GG * DK];
__device__ __align__(16) float g_y[(size_t)BB * TT * DD];
__device__ __align__(16) __nv_bfloat16 g_xh[(size_t)BB * TT * DD];
__device__ __align__(16) __nv_bfloat16 g_xl[(size_t)BB * TT * DD];
__device__ __align__(16) __nv_bfloat16 g_yh[(size_t)BB * TT * DD];
__device__ __align__(16) __nv_bfloat16 g_yl[(size_t)BB * TT * DD];
__device__ __align__(16) __nv_bfloat16 g_wqh[(size_t)DD * DD];
__device__ __align__(16) __nv_bfloat16 g_wql[(size_t)DD * DD];
__device__ __align__(16) __nv_bfloat16 g_wkh[(size_t)512 * DD];
__device__ __align__(16) __nv_bfloat16 g_wkl[(size_t)512 * DD];
__device__ __align__(16) __nv_bfloat16 g_wvh[(size_t)512 * DD];
__device__ __align__(16) __nv_bfloat16 g_wvl[(size_t)512 * DD];
__device__ __align__(16) __nv_bfloat16 g_woh[(size_t)DD * DD];
__device__ __align__(16) __nv_bfloat16 g_wol[(size_t)DD * DD];

// ---------------------------------------------------------------------------
// cp.async helpers (sm_80 baseline — safe on compute_103)
// ---------------------------------------------------------------------------
__device__ __forceinline__ void cp16(uint32_t s, const void* g) {
    asm volatile("cp.async.cg.shared.global [%0], [%1], 16;"
                 :: "r"(s), "l"(__cvta_generic_to_global(g)));
}
#define CP_COMMIT() asm volatile("cp.async.commit_group;" ::: "memory")
#define CP_WAIT(n)  asm volatile("cp.async.wait_group %0;" :: "n"(n) : "memory")

__device__ __forceinline__ uint32_t smem_to_u32(const void* p) {
    uint32_t a;
    asm("{ .reg .u64 t; cvta.to.shared.u64 t, %1; cvt.u32.u64 %0, t; }"
        : "=r"(a) : "l"(p));
    return a;
}

// ---------------------------------------------------------------------------
// Prep kernels: fp32 -> bf16 hi/lo split; weight transpose+split.
// ---------------------------------------------------------------------------
__device__ __forceinline__ void split1(float v, __nv_bfloat16& h, __nv_bfloat16& l) {
    __nv_bfloat16 hb = __float2bfloat16(v);
    h = hb;
    l = __float2bfloat16(v - __bfloat162float(hb));
}

__global__ void split_kernel(const float* __restrict__ x,
                             __nv_bfloat16* __restrict__ h,
                             __nv_bfloat16* __restrict__ l, int n) {
    int i = blockIdx.x * blockDim.x + threadIdx.x;
    if (i < n) split1(x[i], h[i], l[i]);
}

// W [Kd, Nd] row-major -> WT_h/WT_l [Nd, Kd] bf16
__global__ void transpose_split(const float* __restrict__ W,
                                __nv_bfloat16* __restrict__ TH,
                                __nv_bfloat16* __restrict__ TL,
                                int Kd, int Nd) {
    __shared__ float t[32][33];
    int n0 = blockIdx.x * 32, k0 = blockIdx.y * 32;
    int tx = threadIdx.x, ty = threadIdx.y;
    for (int i = ty; i < 32; i += 8)
        t[i][tx] = W[(size_t)(k0 + i) * Nd + n0 + tx];
    __syncthreads();
    for (int i = ty; i < 32; i += 8) {
        float v = t[tx][i];  // = W[k0+tx][n0+i]
        __nv_bfloat16 h, l;
        split1(v, h, l);
        TH[(size_t)(n0 + i) * Kd + k0 + tx] = h;
        TL[(size_t)(n0 + i) * Kd + k0 + tx] = l;
    }
}

// ---------------------------------------------------------------------------
// wmma bf16 hi/lo GEMM: C[M,N] = (Ah+Al)[M,K] @ (Bh+Bl)[N,K]^T, fp32 out.
// CTA tile 128x128x32, 256 threads = 8 warps (4m x 2n), warp tile 32x64.
// 3 MMAs per fragment pair: AhBh + AhBl + AlBh (drops ~2^-22 AlBl term).
// cp.async double-buffered.
// ---------------------------------------------------------------------------
#define GBM 128
#define GBN 128
#define GBK 32
#define GLD 40                       // bf16 elements per smem row (32 + 8 pad)
#define PLANE_B (128 * GLD * 2)      // 10240 bytes per plane
#define STAGE_B (4 * PLANE_B)        // Ah, Al, Bh, Bl
#define GEMM_SMEM (2 * STAGE_B)      // 81920

__global__ __launch_bounds__(256) void gemm_hl(const __nv_bfloat16* __restrict__ Ah,
                                               const __nv_bfloat16* __restrict__ Al,
                                               const __nv_bfloat16* __restrict__ Bh,
                                               const __nv_bfloat16* __restrict__ Bl,
                                               float* __restrict__ C,
                                               int M, int N, int K) {
    extern __shared__ __align__(16) char smem[];
    const uint32_t sb = smem_to_u32(smem);
    const int tid  = threadIdx.x;
    const int warp = tid >> 5;
    const int m0 = blockIdx.y * GBM;
    const int n0 = blockIdx.x * GBN;
    const int wm = (warp >> 1) * 32;   // warp m offset
    const int wn = (warp & 1) * 64;    // warp n offset

    // per-thread cp.async map: 2048 16B chunks per stage -> 8 per thread
    // chunk id: plane (0..3) | row (0..127) | col16 (0..3)
    const __nv_bfloat16* srcs[4] = {Ah + (size_t)m0 * K, Al + (size_t)m0 * K,
                                    Bh + (size_t)n0 * K, Bl + (size_t)n0 * K};

    auto load_stage = [&](int s, int kc) {
        uint32_t base = sb + (uint32_t)s * STAGE_B;
#pragma unroll
        for (int it = 0; it < 8; it++) {
            int id = it * 256 + tid;
            int plane = id >> 9;
            int row   = (id >> 2) & 127;
            int c16   = (id & 3) * 16;            // byte offset within 64B row
            uint32_t dst = base + (uint32_t)plane * PLANE_B +
                           (uint32_t)row * (GLD * 2) + c16;
            cp16(dst, srcs[plane] + (size_t)row * K + kc + (c16 >> 1));
        }
        CP_COMMIT();
    };

    wmma::fragment<wmma::accumulator, 16, 16, 16, float> acc[2][4];
#pragma unroll
    for (int i = 0; i < 2; i++)
#pragma unroll
        for (int j = 0; j < 4; j++) wmma::fill_fragment(acc[i][j], 0.f);

    const int nch = K / GBK;
    load_stage(0, 0);

    for (int ch = 0; ch < nch; ch++) {
        const int s = ch & 1;
        if (ch + 1 < nch) {
            load_stage(s ^ 1, (ch + 1) * GBK);
            CP_WAIT(1);
        } else {
            CP_WAIT(0);
        }
        __syncthreads();

        const __nv_bfloat16* Ahs = (const __nv_bfloat16*)(smem + s * STAGE_B);
        const __nv_bfloat16* Als = (const __nv_bfloat16*)(smem + s * STAGE_B + PLANE_B);
        const __nv_bfloat16* Bhs = (const __nv_bfloat16*)(smem + s * STAGE_B + 2 * PLANE_B);
        const __nv_bfloat16* Bls = (const __nv_bfloat16*)(smem + s * STAGE_B + 3 * PLANE_B);

#pragma unroll
        for (int ks = 0; ks < GBK; ks += 16) {
            wmma::fragment<wmma::matrix_a, 16, 16, 16, __nv_bfloat16, wmma::row_major> ah[2], al[2];
#pragma unroll
            for (int i = 0; i < 2; i++) {
                wmma::load_matrix_sync(ah[i], Ahs + (wm + i * 16) * GLD + ks, GLD);
                wmma::load_matrix_sync(al[i], Als + (wm + i * 16) * GLD + ks, GLD);
            }
#pragma unroll
            for (int j = 0; j < 4; j++) {
                wmma::fragment<wmma::matrix_b, 16, 16, 16, __nv_bfloat16, wmma::col_major> bh, bl;
                wmma::load_matrix_sync(bh, Bhs + (wn + j * 16) * GLD + ks, GLD);
                wmma::load_matrix_sync(bl, Bls + (wn + j * 16) * GLD + ks, GLD);
#pragma unroll
                for (int i = 0; i < 2; i++) {
                    wmma::mma_sync(acc[i][j], ah[i], bh, acc[i][j]);
                    wmma::mma_sync(acc[i][j], ah[i], bl, acc[i][j]);
                    wmma::mma_sync(acc[i][j], al[i], bh, acc[i][j]);
                }
            }
        }
        __syncthreads();
    }

#pragma unroll
    for (int i = 0; i < 2; i++)
#pragma unroll
        for (int j = 0; j < 4; j++)
            wmma::store_matrix_sync(C + (size_t)(m0 + wm + i * 16) * N + n0 + wn + j * 16,
                                    acc[i][j], N, wmma::mem_row_major);
}

// ---------------------------------------------------------------------------
// RoPE (unchanged)
// ---------------------------------------------------------------------------
__global__ void rope_kernel(float* __restrict__ p, int nh, int total) {
    int idx = blockIdx.x * blockDim.x + threadIdx.x;
    if (idx >= total) return;
    int i  = idx & 63;
    int h  = (idx >> 6) % nh;
    int bt = idx / (64 * nh);
    int t  = bt % TT;

    const float log_theta_over_64 = 0.14391156f;
    float freq = __expf(-(float)i * log_theta_over_64);
    float ang  = (float)t * freq;
    float s, c;
    sincosf(ang, &s, &c);

    size_t base = ((size_t)bt * nh + h) * DK;
    float x1 = p[base + i];
    float x2 = p[base + 64 + i];
    p[base + i]      = x1 * c - x2 * s;
    p[base + 64 + i] = x2 * c + x1 * s;
}

// ---------------------------------------------------------------------------
// Flash attention (causal, GQA), TF32 wmma — unchanged from round 2 (passing).
// ---------------------------------------------------------------------------
__device__ __forceinline__ float to_tf32(float x) { return wmma::__float_to_tf32(x); }
__device__ __forceinline__ float4 tf32x4(float4 v) {
    v.x = to_tf32(v.x); v.y = to_tf32(v.y);
    v.z = to_tf32(v.z); v.w = to_tf32(v.w);
    return v;
}

#define QLD 132
#define KLD 68
#define VLD 132
#define SLD 68
#define OLD 132
#define ATT_SMEM ((64 * QLD + 128 * KLD + 64 * VLD + 64 * SLD + 64 * OLD + 192) * 4)

__global__ __launch_bounds__(256) void attn_tc(const float* __restrict__ q,
                                               const float* __restrict__ k,
                                               const float* __restrict__ v,
                                               float* __restrict__ y) {
    const int qt = blockIdx.x;
    const int h  = blockIdx.y;
    const int b  = blockIdx.z;
    const int q0 = qt * 64;
    const int g  = h / RF;

    const int tid  = threadIdx.x;
    const int warp = tid >> 5;

    extern __shared__ __align__(16) float sm[];
    float* Qs   = sm;
    float* Kst  = Qs  + 64 * QLD;
    float* Vs   = Kst + 128 * KLD;
    float* Ss   = Vs  + 64 * VLD;
    float* Os   = Ss  + 64 * SLD;
    float* mrow = Os  + 64 * OLD;
    float* lrow = mrow + 64;
    float* arow = lrow + 64;

    for (int it = tid; it < 64 * 32; it += 256) {
        int row = it >> 5, c4 = (it & 31) * 4;
        float4 val = *(const float4*)(q + (((size_t)(b * TT + q0 + row)) * HH + h) * DK + c4);
        *(float4*)(Qs + row * QLD + c4) = tf32x4(val);
        *(float4*)(Os + row * OLD + c4) = make_float4(0.f, 0.f, 0.f, 0.f);
    }
    if (tid < 64) { mrow[tid] = -1e30f; lrow[tid] = 0.f; }
    __syncthreads();

    const float rs = 0.08838834764831845f;

    for (int kt = 0; kt <= qt; kt++) {
        const int k0 = kt * 64;

        for (int it = tid; it < 64 * 32; it += 256) {
            int key = it >> 5, c4 = (it & 31) * 4;
            float4 kv = *(const float4*)(k + (((size_t)(b * TT + k0 + key)) * GG + g) * DK + c4);
            Kst[(c4 + 0) * KLD + key] = to_tf32(kv.x);
            Kst[(c4 + 1) * KLD + key] = to_tf32(kv.y);
            Kst[(c4 + 2) * KLD + key] = to_tf32(kv.z);
            Kst[(c4 + 3) * KLD + key] = to_tf32(kv.w);
            float4 vv = *(const float4*)(v + (((size_t)(b * TT + k0 + key)) * GG + g) * DK + c4);
            *(float4*)(Vs + key * VLD + c4) = tf32x4(vv);
        }
        __syncthreads();

        {
            const int mt = (warp & 3) * 16;
            const int nb = (warp >> 2) * 32;
            wmma::fragment<wmma::accumulator, 16, 16, 8, float> sa[2];
            wmma::fill_fragment(sa[0], 0.f);
            wmma::fill_fragment(sa[1], 0.f);
#pragma unroll
            for (int kk = 0; kk < 128; kk += 8) {
                wmma::fragment<wmma::matrix_a, 16, 16, 8, wmma::precision::tf32,
                               wmma::row_major> af;
                wmma::load_matrix_sync(af, Qs + mt * QLD + kk, QLD);
#pragma unroll
                for (int j = 0; j < 2; j++) {
                    wmma::fragment<wmma::matrix_b, 16, 16, 8, wmma::precision::tf32,
                                   wmma::row_major> bf;
                    wmma::load_matrix_sync(bf, Kst + kk * KLD + nb + j * 16, KLD);
                    wmma::mma_sync(sa[j], af, bf, sa[j]);
                }
            }
            wmma::store_matrix_sync(Ss + mt * SLD + nb,      sa[0], SLD, wmma::mem_row_major);
            wmma::store_matrix_sync(Ss + mt * SLD + nb + 16, sa[1], SLD, wmma::mem_row_major);
        }
        __syncthreads();

        {
            const int r  = tid >> 2;
            const int qd = tid & 3;
            float mo = mrow[r];
            float sv[16];
            float mx = mo;
#pragma unroll
            for (int j = 0; j < 16; j++) {
                int c = qd * 16 + j;
                float s = Ss[r * SLD + c] * rs;
                if (k0 + c > q0 + r) s = -1e30f;
                sv[j] = s;
                mx = fmaxf(mx, s);
            }
            mx = fmaxf(mx, __shfl_xor_sync(0xffffffffu, mx, 1));
            mx = fmaxf(mx, __shfl_xor_sync(0xffffffffu, mx, 2));
            float sum = 0.f;
#pragma unroll
            for (int j = 0; j < 16; j++) {
                float p = __expf(sv[j] - mx);
                Ss[r * SLD + qd * 16 + j] = p;
                sum += p;
            }
            sum += __shfl_xor_sync(0xffffffffu, sum, 1);
            sum += __shfl_xor_sync(0xffffffffu, sum, 2);
            if (qd == 0) {
                float al = __expf(mo - mx);
                lrow[r] = lrow[r] * al + sum;
                mrow[r] = mx;
                arow[r] = al;
            }
        }
        __syncthreads();

        for (int it = tid; it < 64 * 32; it += 256) {
            int row = it >> 5, c4 = (it & 31) * 4;
            float al = arow[row];
            float4* p = (float4*)(Os + row * OLD + c4);
            float4 o = *p;
            o.x *= al; o.y *= al; o.z *= al; o.w *= al;
            *p = o;
        }
        __syncthreads();

        {
            const int mt = (warp & 3) * 16;
            const int nb = (warp >> 2) * 64;
            wmma::fragment<wmma::accumulator, 16, 16, 8, float> oa[4];
#pragma unroll
            for (int j = 0; j < 4; j++)
                wmma::load_matrix_sync(oa[j], Os + mt * OLD + nb + j * 16, OLD,
                                       wmma::mem_row_major);
#pragma unroll
            for (int kk = 0; kk < 64; kk += 8) {
                wmma::fragment<wmma::matrix_a, 16, 16, 8, wmma::precision::tf32,
                               wmma::row_major> af;
                wmma::load_matrix_sync(af, Ss + mt * SLD + kk, SLD);
#pragma unroll
                for (int j = 0; j < 4; j++) {
                    wmma::fragment<wmma::matrix_b, 16, 16, 8, wmma::precision::tf32,
                                   wmma::row_major> bf;
                    wmma::load_matrix_sync(bf, Vs + kk * VLD + nb + j * 16, VLD);
                    wmma::mma_sync(oa[j], af, bf, oa[j]);
                }
            }
#pragma unroll
            for (int j = 0; j < 4; j++)
                wmma::store_matrix_sync(Os + mt * OLD + nb + j * 16, oa[j], OLD,
                                        wmma::mem_row_major);
        }
        __syncthreads();
    }

    for (int it = tid; it < 64 * 32; it += 256) {
        int row = it >> 5, c4 = (it & 31) * 4;
        float inv = 1.f / lrow[row];
        float4 o = *(const float4*)(Os + row * OLD + c4);
        o.x *= inv; o.y *= inv; o.z *= inv; o.w *= inv;
        *(float4*)(y + ((size_t)(b * TT + q0 + row)) * DD + h * DK + c4) = o;
    }
}

// ---------------------------------------------------------------------------
// Launch
// ---------------------------------------------------------------------------
extern "C" void kernel_launch(void* const* d_in, const int* in_sizes, int n_in,
                              void* d_out, int out_size) {
    const float* x  = (const float*)d_in[0];
    const float* Wq = (const float*)d_in[1];
    const float* Wk = (const float*)d_in[2];
    const float* Wv = (const float*)d_in[3];
    const float* Wo = (const float*)d_in[4];
    float* out = (float*)d_out;

    float *q, *k, *v, *y;
    __nv_bfloat16 *xh, *xl, *yh, *yl;
    __nv_bfloat16 *wqh, *wql, *wkh, *wkl, *wvh, *wvl, *woh, *wol;
    cudaGetSymbolAddress((void**)&q, g_q);
    cudaGetSymbolAddress((void**)&k, g_k);
    cudaGetSymbolAddress((void**)&v, g_v);
    cudaGetSymbolAddress((void**)&y, g_y);
    cudaGetSymbolAddress((void**)&xh, g_xh);
    cudaGetSymbolAddress((void**)&xl, g_xl);
    cudaGetSymbolAddress((void**)&yh, g_yh);
    cudaGetSymbolAddress((void**)&yl, g_yl);
    cudaGetSymbolAddress((void**)&wqh, g_wqh);
    cudaGetSymbolAddress((void**)&wql, g_wql);
    cudaGetSymbolAddress((void**)&wkh, g_wkh);
    cudaGetSymbolAddress((void**)&wkl, g_wkl);
    cudaGetSymbolAddress((void**)&wvh, g_wvh);
    cudaGetSymbolAddress((void**)&wvl, g_wvl);
    cudaGetSymbolAddress((void**)&woh, g_woh);
    cudaGetSymbolAddress((void**)&wol, g_wol);

    const int M = BB * TT;            // 4096
    const int nx = M * DD;

    // Prep: split x, transpose+split weights
    split_kernel<<<(nx + 255) / 256, 256>>>(x, xh, xl, nx);
    transpose_split<<<dim3(DD / 32, DD / 32), dim3(32, 8)>>>(Wq, wqh, wql, DD, DD);
    transpose_split<<<dim3(512 / 32, DD / 32), dim3(32, 8)>>>(Wk, wkh, wkl, DD, 512);
    transpose_split<<<dim3(512 / 32, DD / 32), dim3(32, 8)>>>(Wv, wvh, wvl, DD, 512);
    transpose_split<<<dim3(DD / 32, DD / 32), dim3(32, 8)>>>(Wo, woh, wol, DD, DD);

    cudaFuncSetAttribute(gemm_hl, cudaFuncAttributeMaxDynamicSharedMemorySize, GEMM_SMEM);

    // QKV projections (wmma bf16 hi/lo)
    gemm_hl<<<dim3(DD / GBN, M / GBM), 256, GEMM_SMEM>>>(xh, xl, wqh, wql, q, M, DD, DD);
    gemm_hl<<<dim3(512 / GBN, M / GBM), 256, GEMM_SMEM>>>(xh, xl, wkh, wkl, k, M, 512, DD);
    gemm_hl<<<dim3(512 / GBN, M / GBM), 256, GEMM_SMEM>>>(xh, xl, wvh, wvl, v, M, 512, DD);

    // RoPE
    {
        int tq = BB * TT * HH * 64;
        int tk = BB * TT * GG * 64;
        rope_kernel<<<(tq + 255) / 256, 256>>>(q, HH, tq);
        rope_kernel<<<(tk + 255) / 256, 256>>>(k, GG, tk);
    }

    // Attention
    cudaFuncSetAttribute(attn_tc, cudaFuncAttributeMaxDynamicSharedMemorySize, ATT_SMEM);
    attn_tc<<<dim3(TT / 64, HH, BB), 256, ATT_SMEM>>>(q, k, v, y);

    // Output projection
    split_kernel<<<(nx + 255) / 256, 256>>>(y, yh, yl, nx);
    gemm_hl<<<dim3(DD / GBN, M / GBM), 256, GEMM_SMEM>>>(yh, yl, woh, wol, out, M, DD, DD);
}

// round 5
// speedup vs baseline: 3.1632x; 1.7984x over previous
#include <cuda_runtime.h>
#include <cuda_bf16.h>
#include <cuda_fp16.h>
#include <mma.h>
#include <cstdint>
#include <cstddef>

using namespace nvcuda;

// Problem constants
#define BB 2
#define TT 2048
#define DD 2048
#define HH 16
#define GG 4
#define DK 128
#define RF (HH / GG)   // 4

// ---------------------------------------------------------------------------
// Scratch (__device__ globals; no allocation allowed)
// ---------------------------------------------------------------------------
__device__ __align__(16) float g_q[(size_t)BB * TT * HH * DK];
__device__ __align__(16) float g_k[(size_t)BB * TT * GG * DK];
__device__ __align__(16) float g_v[(size_t)BB * TT * GG * DK];
__device__ __align__(16) float g_y[(size_t)BB * TT * DD];
__device__ __align__(16) __nv_bfloat16 g_xh[(size_t)BB * TT * DD];
__device__ __align__(16) __nv_bfloat16 g_xl[(size_t)BB * TT * DD];
__device__ __align__(16) __nv_bfloat16 g_yh[(size_t)BB * TT * DD];
__device__ __align__(16) __nv_bfloat16 g_yl[(size_t)BB * TT * DD];
__device__ __align__(16) __nv_bfloat16 g_wqh[(size_t)DD * DD];
__device__ __align__(16) __nv_bfloat16 g_wql[(size_t)DD * DD];
__device__ __align__(16) __nv_bfloat16 g_wkh[(size_t)512 * DD];
__device__ __align__(16) __nv_bfloat16 g_wkl[(size_t)512 * DD];
__device__ __align__(16) __nv_bfloat16 g_wvh[(size_t)512 * DD];
__device__ __align__(16) __nv_bfloat16 g_wvl[(size_t)512 * DD];
__device__ __align__(16) __nv_bfloat16 g_woh[(size_t)DD * DD];
__device__ __align__(16) __nv_bfloat16 g_wol[(size_t)DD * DD];

// ---------------------------------------------------------------------------
// PTX helpers
// ---------------------------------------------------------------------------
__device__ __forceinline__ void cp16(uint32_t s, const void* g) {
    asm volatile("cp.async.cg.shared.global [%0], [%1], 16;"
                 :: "r"(s), "l"(__cvta_generic_to_global(g)));
}
#define CP_COMMIT() asm volatile("cp.async.commit_group;" ::: "memory")
#define CP_WAIT(n)  asm volatile("cp.async.wait_group %0;" :: "n"(n) : "memory")

__device__ __forceinline__ uint32_t smem_to_u32(const void* p) {
    uint32_t a;
    asm("{ .reg .u64 t; cvta.to.shared.u64 t, %1; cvt.u32.u64 %0, t; }"
        : "=r"(a) : "l"(p));
    return a;
}

__device__ __forceinline__ void mma16816(float* d, const uint32_t* a, const uint32_t* b) {
    asm volatile("mma.sync.aligned.m16n8k16.row.col.f32.f16.f16.f32 "
        "{%0,%1,%2,%3}, {%4,%5,%6,%7}, {%8,%9}, {%0,%1,%2,%3};"
        : "+f"(d[0]), "+f"(d[1]), "+f"(d[2]), "+f"(d[3])
        : "r"(a[0]), "r"(a[1]), "r"(a[2]), "r"(a[3]), "r"(b[0]), "r"(b[1]));
}
__device__ __forceinline__ void ldsm4(uint32_t* r, uint32_t addr) {
    asm volatile("ldmatrix.sync.aligned.m8n8.x4.shared.b16 {%0,%1,%2,%3}, [%4];"
        : "=r"(r[0]), "=r"(r[1]), "=r"(r[2]), "=r"(r[3]) : "r"(addr));
}
__device__ __forceinline__ void ldsm4t(uint32_t* r, uint32_t addr) {
    asm volatile("ldmatrix.sync.aligned.m8n8.x4.trans.shared.b16 {%0,%1,%2,%3}, [%4];"
        : "=r"(r[0]), "=r"(r[1]), "=r"(r[2]), "=r"(r[3]) : "r"(addr));
}
__device__ __forceinline__ uint32_t packh2(float a, float b) {
    __half2 h = __floats2half2_rn(a, b);
    return *(uint32_t*)&h;
}

// ---------------------------------------------------------------------------
// Prep kernels: fp32 -> bf16 hi/lo split; weight transpose+split.
// ---------------------------------------------------------------------------
__device__ __forceinline__ void split1(float v, __nv_bfloat16& h, __nv_bfloat16& l) {
    __nv_bfloat16 hb = __float2bfloat16(v);
    h = hb;
    l = __float2bfloat16(v - __bfloat162float(hb));
}

__global__ void split_kernel(const float* __restrict__ x,
                             __nv_bfloat16* __restrict__ h,
                             __nv_bfloat16* __restrict__ l, int n) {
    int i = blockIdx.x * blockDim.x + threadIdx.x;
    if (i < n) split1(x[i], h[i], l[i]);
}

__global__ void transpose_split(const float* __restrict__ W,
                                __nv_bfloat16* __restrict__ TH,
                                __nv_bfloat16* __restrict__ TL,
                                int Kd, int Nd) {
    __shared__ float t[32][33];
    int n0 = blockIdx.x * 32, k0 = blockIdx.y * 32;
    int tx = threadIdx.x, ty = threadIdx.y;
    for (int i = ty; i < 32; i += 8)
        t[i][tx] = W[(size_t)(k0 + i) * Nd + n0 + tx];
    __syncthreads();
    for (int i = ty; i < 32; i += 8) {
        float v = t[tx][i];
        __nv_bfloat16 h, l;
        split1(v, h, l);
        TH[(size_t)(n0 + i) * Kd + k0 + tx] = h;
        TL[(size_t)(n0 + i) * Kd + k0 + tx] = l;
    }
}

// ---------------------------------------------------------------------------
// wmma bf16 hi/lo GEMM (unchanged from round 4)
// ---------------------------------------------------------------------------
#define GBM 128
#define GBN 128
#define GBK 32
#define GLD 40
#define PLANE_B (128 * GLD * 2)
#define STAGE_B (4 * PLANE_B)
#define GEMM_SMEM (2 * STAGE_B)

__global__ __launch_bounds__(256) void gemm_hl(const __nv_bfloat16* __restrict__ Ah,
                                               const __nv_bfloat16* __restrict__ Al,
                                               const __nv_bfloat16* __restrict__ Bh,
                                               const __nv_bfloat16* __restrict__ Bl,
                                               float* __restrict__ C,
                                               int M, int N, int K) {
    extern __shared__ __align__(16) char smem[];
    const uint32_t sb = smem_to_u32(smem);
    const int tid  = threadIdx.x;
    const int warp = tid >> 5;
    const int m0 = blockIdx.y * GBM;
    const int n0 = blockIdx.x * GBN;
    const int wm = (warp >> 1) * 32;
    const int wn = (warp & 1) * 64;

    const __nv_bfloat16* srcs[4] = {Ah + (size_t)m0 * K, Al + (size_t)m0 * K,
                                    Bh + (size_t)n0 * K, Bl + (size_t)n0 * K};

    auto load_stage = [&](int s, int kc) {
        uint32_t base = sb + (uint32_t)s * STAGE_B;
#pragma unroll
        for (int it = 0; it < 8; it++) {
            int id = it * 256 + tid;
            int plane = id >> 9;
            int row   = (id >> 2) & 127;
            int c16   = (id & 3) * 16;
            uint32_t dst = base + (uint32_t)plane * PLANE_B +
                           (uint32_t)row * (GLD * 2) + c16;
            cp16(dst, srcs[plane] + (size_t)row * K + kc + (c16 >> 1));
        }
        CP_COMMIT();
    };

    wmma::fragment<wmma::accumulator, 16, 16, 16, float> acc[2][4];
#pragma unroll
    for (int i = 0; i < 2; i++)
#pragma unroll
        for (int j = 0; j < 4; j++) wmma::fill_fragment(acc[i][j], 0.f);

    const int nch = K / GBK;
    load_stage(0, 0);

    for (int ch = 0; ch < nch; ch++) {
        const int s = ch & 1;
        if (ch + 1 < nch) {
            load_stage(s ^ 1, (ch + 1) * GBK);
            CP_WAIT(1);
        } else {
            CP_WAIT(0);
        }
        __syncthreads();

        const __nv_bfloat16* Ahs = (const __nv_bfloat16*)(smem + s * STAGE_B);
        const __nv_bfloat16* Als = (const __nv_bfloat16*)(smem + s * STAGE_B + PLANE_B);
        const __nv_bfloat16* Bhs = (const __nv_bfloat16*)(smem + s * STAGE_B + 2 * PLANE_B);
        const __nv_bfloat16* Bls = (const __nv_bfloat16*)(smem + s * STAGE_B + 3 * PLANE_B);

#pragma unroll
        for (int ks = 0; ks < GBK; ks += 16) {
            wmma::fragment<wmma::matrix_a, 16, 16, 16, __nv_bfloat16, wmma::row_major> ah[2], al[2];
#pragma unroll
            for (int i = 0; i < 2; i++) {
                wmma::load_matrix_sync(ah[i], Ahs + (wm + i * 16) * GLD + ks, GLD);
                wmma::load_matrix_sync(al[i], Als + (wm + i * 16) * GLD + ks, GLD);
            }
#pragma unroll
            for (int j = 0; j < 4; j++) {
                wmma::fragment<wmma::matrix_b, 16, 16, 16, __nv_bfloat16, wmma::col_major> bh, bl;
                wmma::load_matrix_sync(bh, Bhs + (wn + j * 16) * GLD + ks, GLD);
                wmma::load_matrix_sync(bl, Bls + (wn + j * 16) * GLD + ks, GLD);
#pragma unroll
                for (int i = 0; i < 2; i++) {
                    wmma::mma_sync(acc[i][j], ah[i], bh, acc[i][j]);
                    wmma::mma_sync(acc[i][j], ah[i], bl, acc[i][j]);
                    wmma::mma_sync(acc[i][j], al[i], bh, acc[i][j]);
                }
            }
        }
        __syncthreads();
    }

#pragma unroll
    for (int i = 0; i < 2; i++)
#pragma unroll
        for (int j = 0; j < 4; j++)
            wmma::store_matrix_sync(C + (size_t)(m0 + wm + i * 16) * N + n0 + wn + j * 16,
                                    acc[i][j], N, wmma::mem_row_major);
}

// ---------------------------------------------------------------------------
// RoPE (unchanged)
// ---------------------------------------------------------------------------
__global__ void rope_kernel(float* __restrict__ p, int nh, int total) {
    int idx = blockIdx.x * blockDim.x + threadIdx.x;
    if (idx >= total) return;
    int i  = idx & 63;
    int h  = (idx >> 6) % nh;
    int bt = idx / (64 * nh);
    int t  = bt % TT;

    const float log_theta_over_64 = 0.14391156f;
    float freq = __expf(-(float)i * log_theta_over_64);
    float ang  = (float)t * freq;
    float s, c;
    sincosf(ang, &s, &c);

    size_t base = ((size_t)bt * nh + h) * DK;
    float x1 = p[base + i];
    float x2 = p[base + 64 + i];
    p[base + i]      = x1 * c - x2 * s;
    p[base + 64 + i] = x2 * c + x1 * s;
}

// ---------------------------------------------------------------------------
// Flash attention (causal, GQA): fp16 mma.m16n8k16, register-resident O,
// P reused from S registers (no smem round trip). 128 threads = 4 warps,
// each warp owns 16 q-rows. BQ=64, BK=64.
// ---------------------------------------------------------------------------
#define KP 136   // smem row pitch in halves (128 + 8) -> conflict-free ldmatrix

__global__ __launch_bounds__(128, 2) void attn_h(const float* __restrict__ q,
                                                 const float* __restrict__ k,
                                                 const float* __restrict__ v,
                                                 float* __restrict__ y) {
    __shared__ __align__(16) __half Ks[64 * KP];
    __shared__ __align__(16) __half Vs[64 * KP];

    const int qt = (int)gridDim.x - 1 - (int)blockIdx.x;  // longest first
    const int h  = blockIdx.y;
    const int b  = blockIdx.z;
    const int q0 = qt * 64;
    const int g  = h / RF;

    const int tid  = threadIdx.x;
    const int lane = tid & 31;
    const int warp = tid >> 5;
    const int wrow = warp * 16;
    const float rs = 0.08838834764831845f;  // 1/sqrt(128)

    // Stage Q (pre-scaled, fp16) into Ks, then build A-fragments.
    for (int i = tid; i < 64 * 32; i += 128) {
        int row = i >> 5, c4 = (i & 31) * 4;
        float4 f = *(const float4*)(q + (((size_t)(b * TT + q0 + row)) * HH + h) * DK + c4);
        uint2 u = make_uint2(packh2(f.x * rs, f.y * rs), packh2(f.z * rs, f.w * rs));
        *(uint2*)(Ks + row * KP + c4) = u;
    }
    __syncthreads();

    const int mm   = lane >> 3;                 // matrix id 0..3
    const int arow = (mm & 1) * 8 + (lane & 7); // A/V-trans row offset
    const int acol = (mm >> 1) * 8;             // A/V-trans col offset
    const int brow = (mm >> 1) * 8 + (lane & 7);// QKT-B row (key) offset
    const int bcol = (mm & 1) * 8;              // QKT-B col (d) offset

    uint32_t Qa[8][4];
#pragma unroll
    for (int kc = 0; kc < 8; kc++)
        ldsm4(Qa[kc], smem_to_u32(Ks + (wrow + arow) * KP + kc * 16 + acol));
    __syncthreads();

    float Ofr[16][4];
#pragma unroll
    for (int nb = 0; nb < 16; nb++)
#pragma unroll
        for (int j = 0; j < 4; j++) Ofr[nb][j] = 0.f;

    float m0r = -1e30f, m1r = -1e30f, l0r = 0.f, l1r = 0.f;
    const int r0 = lane >> 2;
    const int c0 = (lane & 3) * 2;

    for (int kt = 0; kt <= qt; kt++) {
        const int k0 = kt * 64;

        // Load K, V tiles (fp32 -> fp16)
        for (int i = tid; i < 64 * 32; i += 128) {
            int row = i >> 5, c4 = (i & 31) * 4;
            size_t gi = (((size_t)(b * TT + k0 + row)) * GG + g) * DK + c4;
            float4 fk = *(const float4*)(k + gi);
            float4 fv = *(const float4*)(v + gi);
            *(uint2*)(Ks + row * KP + c4) = make_uint2(packh2(fk.x, fk.y), packh2(fk.z, fk.w));
            *(uint2*)(Vs + row * KP + c4) = make_uint2(packh2(fv.x, fv.y), packh2(fv.z, fv.w));
        }
        __syncthreads();

        // S = Q @ K^T  (16 x 64 per warp)
        float S[8][4];
#pragma unroll
        for (int nb = 0; nb < 8; nb++)
#pragma unroll
            for (int j = 0; j < 4; j++) S[nb][j] = 0.f;

#pragma unroll
        for (int kc = 0; kc < 8; kc++)
#pragma unroll
            for (int nbp = 0; nbp < 4; nbp++) {
                uint32_t bb[4];
                ldsm4(bb, smem_to_u32(Ks + (nbp * 16 + brow) * KP + kc * 16 + bcol));
                mma16816(S[2 * nbp],     Qa[kc], bb);
                mma16816(S[2 * nbp + 1], Qa[kc], bb + 2);
            }

        // Causal mask on diagonal tile (k0 == q0)
        if (kt == qt) {
            const int rl0 = wrow + r0, rl1 = rl0 + 8;
#pragma unroll
            for (int nb = 0; nb < 8; nb++) {
                int colb = nb * 8 + c0;
                if (colb     > rl0) S[nb][0] = -1e30f;
                if (colb + 1 > rl0) S[nb][1] = -1e30f;
                if (colb     > rl1) S[nb][2] = -1e30f;
                if (colb + 1 > rl1) S[nb][3] = -1e30f;
            }
        }

        // Online softmax (rows r0, r0+8 of warp block; quad = 4 lanes/row)
        float mx0 = -1e30f, mx1 = -1e30f;
#pragma unroll
        for (int nb = 0; nb < 8; nb++) {
            mx0 = fmaxf(mx0, fmaxf(S[nb][0], S[nb][1]));
            mx1 = fmaxf(mx1, fmaxf(S[nb][2], S[nb][3]));
        }
        mx0 = fmaxf(mx0, __shfl_xor_sync(0xffffffffu, mx0, 1));
        mx0 = fmaxf(mx0, __shfl_xor_sync(0xffffffffu, mx0, 2));
        mx1 = fmaxf(mx1, __shfl_xor_sync(0xffffffffu, mx1, 1));
        mx1 = fmaxf(mx1, __shfl_xor_sync(0xffffffffu, mx1, 2));

        float mn0 = fmaxf(m0r, mx0), mn1 = fmaxf(m1r, mx1);
        float a0 = __expf(m0r - mn0), a1 = __expf(m1r - mn1);
        float s0 = 0.f, s1 = 0.f;
#pragma unroll
        for (int nb = 0; nb < 8; nb++) {
            S[nb][0] = __expf(S[nb][0] - mn0);
            S[nb][1] = __expf(S[nb][1] - mn0);
            S[nb][2] = __expf(S[nb][2] - mn1);
            S[nb][3] = __expf(S[nb][3] - mn1);
            s0 += S[nb][0] + S[nb][1];
            s1 += S[nb][2] + S[nb][3];
        }
        s0 += __shfl_xor_sync(0xffffffffu, s0, 1);
        s0 += __shfl_xor_sync(0xffffffffu, s0, 2);
        s1 += __shfl_xor_sync(0xffffffffu, s1, 1);
        s1 += __shfl_xor_sync(0xffffffffu, s1, 2);
        l0r = l0r * a0 + s0;
        l1r = l1r * a1 + s1;
        m0r = mn0; m1r = mn1;

        // Rescale register-resident O
#pragma unroll
        for (int nb = 0; nb < 16; nb++) {
            Ofr[nb][0] *= a0; Ofr[nb][1] *= a0;
            Ofr[nb][2] *= a1; Ofr[nb][3] *= a1;
        }

        // P (fp16 A-fragments) directly from S registers
        uint32_t Pa[4][4];
#pragma unroll
        for (int kc = 0; kc < 4; kc++) {
            Pa[kc][0] = packh2(S[2 * kc][0],     S[2 * kc][1]);
            Pa[kc][1] = packh2(S[2 * kc][2],     S[2 * kc][3]);
            Pa[kc][2] = packh2(S[2 * kc + 1][0], S[2 * kc + 1][1]);
            Pa[kc][3] = packh2(S[2 * kc + 1][2], S[2 * kc + 1][3]);
        }

        // O += P @ V  (ldmatrix.trans gives B-fragments from key-major V)
#pragma unroll
        for (int kc = 0; kc < 4; kc++)
#pragma unroll
            for (int nbp = 0; nbp < 8; nbp++) {
                uint32_t bb[4];
                ldsm4t(bb, smem_to_u32(Vs + (kc * 16 + arow) * KP + nbp * 16 + acol));
                mma16816(Ofr[2 * nbp],     Pa[kc], bb);
                mma16816(Ofr[2 * nbp + 1], Pa[kc], bb + 2);
            }
        __syncthreads();  // protect Ks/Vs before next tile's loads
    }

    // Epilogue: normalize, write y (b, t, h*128 + d)
    const float i0 = 1.f / l0r, i1 = 1.f / l1r;
#pragma unroll
    for (int nb = 0; nb < 16; nb++) {
        size_t base0 = ((size_t)(b * TT + q0 + wrow + r0)) * DD + h * DK + nb * 8 + c0;
        size_t base1 = base0 + (size_t)8 * DD;
        float2 o0 = make_float2(Ofr[nb][0] * i0, Ofr[nb][1] * i0);
        float2 o1 = make_float2(Ofr[nb][2] * i1, Ofr[nb][3] * i1);
        *(float2*)(y + base0) = o0;
        *(float2*)(y + base1) = o1;
    }
}

// ---------------------------------------------------------------------------
// Launch
// ---------------------------------------------------------------------------
extern "C" void kernel_launch(void* const* d_in, const int* in_sizes, int n_in,
                              void* d_out, int out_size) {
    const float* x  = (const float*)d_in[0];
    const float* Wq = (const float*)d_in[1];
    const float* Wk = (const float*)d_in[2];
    const float* Wv = (const float*)d_in[3];
    const float* Wo = (const float*)d_in[4];
    float* out = (float*)d_out;

    float *q, *k, *v, *y;
    __nv_bfloat16 *xh, *xl, *yh, *yl;
    __nv_bfloat16 *wqh, *wql, *wkh, *wkl, *wvh, *wvl, *woh, *wol;
    cudaGetSymbolAddress((void**)&q, g_q);
    cudaGetSymbolAddress((void**)&k, g_k);
    cudaGetSymbolAddress((void**)&v, g_v);
    cudaGetSymbolAddress((void**)&y, g_y);
    cudaGetSymbolAddress((void**)&xh, g_xh);
    cudaGetSymbolAddress((void**)&xl, g_xl);
    cudaGetSymbolAddress((void**)&yh, g_yh);
    cudaGetSymbolAddress((void**)&yl, g_yl);
    cudaGetSymbolAddress((void**)&wqh, g_wqh);
    cudaGetSymbolAddress((void**)&wql, g_wql);
    cudaGetSymbolAddress((void**)&wkh, g_wkh);
    cudaGetSymbolAddress((void**)&wkl, g_wkl);
    cudaGetSymbolAddress((void**)&wvh, g_wvh);
    cudaGetSymbolAddress((void**)&wvl, g_wvl);
    cudaGetSymbolAddress((void**)&woh, g_woh);
    cudaGetSymbolAddress((void**)&wol, g_wol);

    const int M = BB * TT;            // 4096
    const int nx = M * DD;

    // Prep: split x, transpose+split weights
    split_kernel<<<(nx + 255) / 256, 256>>>(x, xh, xl, nx);
    transpose_split<<<dim3(DD / 32, DD / 32), dim3(32, 8)>>>(Wq, wqh, wql, DD, DD);
    transpose_split<<<dim3(512 / 32, DD / 32), dim3(32, 8)>>>(Wk, wkh, wkl, DD, 512);
    transpose_split<<<dim3(512 / 32, DD / 32), dim3(32, 8)>>>(Wv, wvh, wvl, DD, 512);
    transpose_split<<<dim3(DD / 32, DD / 32), dim3(32, 8)>>>(Wo, woh, wol, DD, DD);

    cudaFuncSetAttribute(gemm_hl, cudaFuncAttributeMaxDynamicSharedMemorySize, GEMM_SMEM);

    // QKV projections (wmma bf16 hi/lo)
    gemm_hl<<<dim3(DD / GBN, M / GBM), 256, GEMM_SMEM>>>(xh, xl, wqh, wql, q, M, DD, DD);
    gemm_hl<<<dim3(512 / GBN, M / GBM), 256, GEMM_SMEM>>>(xh, xl, wkh, wkl, k, M, 512, DD);
    gemm_hl<<<dim3(512 / GBN, M / GBM), 256, GEMM_SMEM>>>(xh, xl, wvh, wvl, v, M, 512, DD);

    // RoPE
    {
        int tq = BB * TT * HH * 64;
        int tk = BB * TT * GG * 64;
        rope_kernel<<<(tq + 255) / 256, 256>>>(q, HH, tq);
        rope_kernel<<<(tk + 255) / 256, 256>>>(k, GG, tk);
    }

    // Attention (fp16 mma, register-resident O)
    attn_h<<<dim3(TT / 64, HH, BB), 128>>>(q, k, v, y);

    // Output projection
    split_kernel<<<(nx + 255) / 256, 256>>>(y, yh, yl, nx);
    gemm_hl<<<dim3(DD / GBN, M / GBM), 256, GEMM_SMEM>>>(yh, yl, woh, wol, out, M, DD, DD);
}

// round 6
// speedup vs baseline: 3.4212x; 1.0816x over previous
#include <cuda_runtime.h>
#include <cuda_bf16.h>
#include <cuda_fp16.h>
#include <mma.h>
#include <cstdint>
#include <cstddef>

using namespace nvcuda;

// Problem constants
#define BB 2
#define TT 2048
#define DD 2048
#define HH 16
#define GG 4
#define DK 128
#define RF (HH / GG)   // 4

// ---------------------------------------------------------------------------
// Scratch (__device__ globals; no allocation allowed)
// ---------------------------------------------------------------------------
__device__ __align__(16) float g_qkv[(size_t)BB * TT * 3072];      // fused QKV out
__device__ __align__(16) __half g_qh[(size_t)BB * TT * DD];
__device__ __align__(16) __half g_kh[(size_t)BB * TT * 512];
__device__ __align__(16) __half g_vh[(size_t)BB * TT * 512];
__device__ __align__(16) __nv_bfloat16 g_xh[(size_t)BB * TT * DD];
__device__ __align__(16) __nv_bfloat16 g_xl[(size_t)BB * TT * DD];
__device__ __align__(16) __nv_bfloat16 g_yh[(size_t)BB * TT * DD];
__device__ __align__(16) __nv_bfloat16 g_yl[(size_t)BB * TT * DD];
__device__ __align__(16) __nv_bfloat16 g_wth[(size_t)3072 * DD];   // [Wq;Wk;Wv]^T hi
__device__ __align__(16) __nv_bfloat16 g_wtl[(size_t)3072 * DD];   // lo
__device__ __align__(16) __nv_bfloat16 g_woh[(size_t)DD * DD];
__device__ __align__(16) __nv_bfloat16 g_wol[(size_t)DD * DD];

// ---------------------------------------------------------------------------
// PTX helpers
// ---------------------------------------------------------------------------
__device__ __forceinline__ void cp16(uint32_t s, const void* g) {
    asm volatile("cp.async.cg.shared.global [%0], [%1], 16;"
                 :: "r"(s), "l"(__cvta_generic_to_global(g)));
}
#define CP_COMMIT() asm volatile("cp.async.commit_group;" ::: "memory")
#define CP_WAIT(n)  asm volatile("cp.async.wait_group %0;" :: "n"(n) : "memory")

__device__ __forceinline__ uint32_t smem_to_u32(const void* p) {
    uint32_t a;
    asm("{ .reg .u64 t; cvta.to.shared.u64 t, %1; cvt.u32.u64 %0, t; }"
        : "=r"(a) : "l"(p));
    return a;
}

__device__ __forceinline__ void mma16816(float* d, const uint32_t* a, const uint32_t* b) {
    asm volatile("mma.sync.aligned.m16n8k16.row.col.f32.f16.f16.f32 "
        "{%0,%1,%2,%3}, {%4,%5,%6,%7}, {%8,%9}, {%0,%1,%2,%3};"
        : "+f"(d[0]), "+f"(d[1]), "+f"(d[2]), "+f"(d[3])
        : "r"(a[0]), "r"(a[1]), "r"(a[2]), "r"(a[3]), "r"(b[0]), "r"(b[1]));
}
__device__ __forceinline__ void ldsm4(uint32_t* r, uint32_t addr) {
    asm volatile("ldmatrix.sync.aligned.m8n8.x4.shared.b16 {%0,%1,%2,%3}, [%4];"
        : "=r"(r[0]), "=r"(r[1]), "=r"(r[2]), "=r"(r[3]) : "r"(addr));
}
__device__ __forceinline__ void ldsm4t(uint32_t* r, uint32_t addr) {
    asm volatile("ldmatrix.sync.aligned.m8n8.x4.trans.shared.b16 {%0,%1,%2,%3}, [%4];"
        : "=r"(r[0]), "=r"(r[1]), "=r"(r[2]), "=r"(r[3]) : "r"(addr));
}
__device__ __forceinline__ uint32_t packh2(float a, float b) {
    __half2 h = __floats2half2_rn(a, b);
    return *(uint32_t*)&h;
}

// ---------------------------------------------------------------------------
// Prep kernels
// ---------------------------------------------------------------------------
__device__ __forceinline__ void split1(float v, __nv_bfloat16& h, __nv_bfloat16& l) {
    __nv_bfloat16 hb = __float2bfloat16(v);
    h = hb;
    l = __float2bfloat16(v - __bfloat162float(hb));
}

__global__ void split_kernel(const float* __restrict__ x,
                             __nv_bfloat16* __restrict__ h,
                             __nv_bfloat16* __restrict__ l, int n) {
    int i = blockIdx.x * blockDim.x + threadIdx.x;
    if (i < n) split1(x[i], h[i], l[i]);
}

__global__ void transpose_split(const float* __restrict__ W,
                                __nv_bfloat16* __restrict__ TH,
                                __nv_bfloat16* __restrict__ TL,
                                int Kd, int Nd) {
    __shared__ float t[32][33];
    int n0 = blockIdx.x * 32, k0 = blockIdx.y * 32;
    int tx = threadIdx.x, ty = threadIdx.y;
    for (int i = ty; i < 32; i += 8)
        t[i][tx] = W[(size_t)(k0 + i) * Nd + n0 + tx];
    __syncthreads();
    for (int i = ty; i < 32; i += 8) {
        float v = t[tx][i];
        __nv_bfloat16 h, l;
        split1(v, h, l);
        TH[(size_t)(n0 + i) * Kd + k0 + tx] = h;
        TL[(size_t)(n0 + i) * Kd + k0 + tx] = l;
    }
}

// RoPE from fused qkv (fp32, row stride 3072) -> fp16, optional scale.
__global__ void rope_h(const float* __restrict__ src, __half* __restrict__ dst,
                       int nh, int ostride, float scale, int total) {
    int idx = blockIdx.x * blockDim.x + threadIdx.x;
    if (idx >= total) return;
    int i  = idx & 63;
    int h  = (idx >> 6) % nh;
    int bt = idx / (64 * nh);
    int t  = bt % TT;

    const float log_theta_over_64 = 0.14391156f;
    float freq = __expf(-(float)i * log_theta_over_64);
    float ang  = (float)t * freq;
    float s, c;
    sincosf(ang, &s, &c);

    size_t sbase = (size_t)bt * 3072 + h * DK;
    float x1 = src[sbase + i];
    float x2 = src[sbase + 64 + i];
    size_t obase = (size_t)bt * ostride + h * DK;
    dst[obase + i]      = __float2half((x1 * c - x2 * s) * scale);
    dst[obase + 64 + i] = __float2half((x2 * c + x1 * s) * scale);
}

// v: fp32 (qkv cols 2560:3072) -> fp16
__global__ void conv_v(const float* __restrict__ src, __half* __restrict__ dst, int total) {
    int idx = blockIdx.x * blockDim.x + threadIdx.x;
    if (idx >= total) return;
    int row = idx >> 9, col = idx & 511;
    dst[(size_t)row * 512 + col] = __float2half(src[(size_t)row * 3072 + 2560 + col]);
}

// ---------------------------------------------------------------------------
// wmma bf16 hi/lo GEMM, 3-stage cp.async pipeline.
// ---------------------------------------------------------------------------
#define GBM 128
#define GBN 128
#define GBK 32
#define GLD 40
#define PLANE_B (128 * GLD * 2)
#define STAGE_B (4 * PLANE_B)
#define GEMM_SMEM (3 * STAGE_B)

__global__ __launch_bounds__(256) void gemm_hl(const __nv_bfloat16* __restrict__ Ah,
                                               const __nv_bfloat16* __restrict__ Al,
                                               const __nv_bfloat16* __restrict__ Bh,
                                               const __nv_bfloat16* __restrict__ Bl,
                                               float* __restrict__ C,
                                               int M, int N, int K) {
    extern __shared__ __align__(16) char smem[];
    const uint32_t sb = smem_to_u32(smem);
    const int tid  = threadIdx.x;
    const int warp = tid >> 5;
    const int m0 = blockIdx.y * GBM;
    const int n0 = blockIdx.x * GBN;
    const int wm = (warp >> 1) * 32;
    const int wn = (warp & 1) * 64;

    const __nv_bfloat16* srcs[4] = {Ah + (size_t)m0 * K, Al + (size_t)m0 * K,
                                    Bh + (size_t)n0 * K, Bl + (size_t)n0 * K};

    auto load_stage = [&](int s, int kc) {
        uint32_t base = sb + (uint32_t)s * STAGE_B;
#pragma unroll
        for (int it = 0; it < 8; it++) {
            int id = it * 256 + tid;
            int plane = id >> 9;
            int row   = (id >> 2) & 127;
            int c16   = (id & 3) * 16;
            uint32_t dst = base + (uint32_t)plane * PLANE_B +
                           (uint32_t)row * (GLD * 2) + c16;
            cp16(dst, srcs[plane] + (size_t)row * K + kc + (c16 >> 1));
        }
        CP_COMMIT();
    };

    wmma::fragment<wmma::accumulator, 16, 16, 16, float> acc[2][4];
#pragma unroll
    for (int i = 0; i < 2; i++)
#pragma unroll
        for (int j = 0; j < 4; j++) wmma::fill_fragment(acc[i][j], 0.f);

    const int nch = K / GBK;
    load_stage(0, 0);
    load_stage(1, GBK);

    for (int ch = 0; ch < nch; ch++) {
        const int s = ch % 3;
        if (ch + 2 < nch) {
            load_stage((ch + 2) % 3, (ch + 2) * GBK);
            CP_WAIT(2);
        } else if (ch + 1 < nch) {
            CP_WAIT(1);
        } else {
            CP_WAIT(0);
        }
        __syncthreads();

        const __nv_bfloat16* Ahs = (const __nv_bfloat16*)(smem + s * STAGE_B);
        const __nv_bfloat16* Als = (const __nv_bfloat16*)(smem + s * STAGE_B + PLANE_B);
        const __nv_bfloat16* Bhs = (const __nv_bfloat16*)(smem + s * STAGE_B + 2 * PLANE_B);
        const __nv_bfloat16* Bls = (const __nv_bfloat16*)(smem + s * STAGE_B + 3 * PLANE_B);

#pragma unroll
        for (int ks = 0; ks < GBK; ks += 16) {
            wmma::fragment<wmma::matrix_a, 16, 16, 16, __nv_bfloat16, wmma::row_major> ah[2], al[2];
#pragma unroll
            for (int i = 0; i < 2; i++) {
                wmma::load_matrix_sync(ah[i], Ahs + (wm + i * 16) * GLD + ks, GLD);
                wmma::load_matrix_sync(al[i], Als + (wm + i * 16) * GLD + ks, GLD);
            }
#pragma unroll
            for (int j = 0; j < 4; j++) {
                wmma::fragment<wmma::matrix_b, 16, 16, 16, __nv_bfloat16, wmma::col_major> bh, bl;
                wmma::load_matrix_sync(bh, Bhs + (wn + j * 16) * GLD + ks, GLD);
                wmma::load_matrix_sync(bl, Bls + (wn + j * 16) * GLD + ks, GLD);
#pragma unroll
                for (int i = 0; i < 2; i++) {
                    wmma::mma_sync(acc[i][j], ah[i], bh, acc[i][j]);
                    wmma::mma_sync(acc[i][j], ah[i], bl, acc[i][j]);
                    wmma::mma_sync(acc[i][j], al[i], bh, acc[i][j]);
                }
            }
        }
        __syncthreads();
    }

#pragma unroll
    for (int i = 0; i < 2; i++)
#pragma unroll
        for (int j = 0; j < 4; j++)
            wmma::store_matrix_sync(C + (size_t)(m0 + wm + i * 16) * N + n0 + wn + j * 16,
                                    acc[i][j], N, wmma::mem_row_major);
}

// ---------------------------------------------------------------------------
// Flash attention: fp16 inputs, cp.async double-buffered K/V, register O,
// epilogue writes bf16 hi/lo directly. 128 threads = 4 warps, BQ=BK=64.
// ---------------------------------------------------------------------------
#define KP 136
#define ATILE_H (64 * KP)                 // halves per tile buffer
#define ATT_SMEM (4 * ATILE_H * 2)        // K0,K1,V0,V1 bytes = 69632

__global__ __launch_bounds__(128, 2) void attn_h(const __half* __restrict__ q,
                                                 const __half* __restrict__ k,
                                                 const __half* __restrict__ v,
                                                 __nv_bfloat16* __restrict__ yh,
                                                 __nv_bfloat16* __restrict__ yl) {
    extern __shared__ __align__(16) __half asm_[];
    __half* KsA[2] = {asm_, asm_ + ATILE_H};
    __half* VsA[2] = {asm_ + 2 * ATILE_H, asm_ + 3 * ATILE_H};

    const int qt = (int)gridDim.x - 1 - (int)blockIdx.x;  // longest first
    const int h  = blockIdx.y;
    const int b  = blockIdx.z;
    const int q0 = qt * 64;
    const int g  = h / RF;

    const int tid  = threadIdx.x;
    const int lane = tid & 31;
    const int warp = tid >> 5;
    const int wrow = warp * 16;

    // Stage Q (already scaled by 1/sqrt(dk) in rope_h) into KsA[0].
    for (int i = tid; i < 64 * 16; i += 128) {
        int row = i >> 4, c8 = (i & 15) * 8;
        *(uint4*)(KsA[0] + row * KP + c8) =
            *(const uint4*)(q + ((size_t)(b * TT + q0 + row)) * DD + h * DK + c8);
    }
    __syncthreads();

    const int mm   = lane >> 3;
    const int arow = (mm & 1) * 8 + (lane & 7);
    const int acol = (mm >> 1) * 8;
    const int brow = (mm >> 1) * 8 + (lane & 7);
    const int bcol = (mm & 1) * 8;

    uint32_t Qa[8][4];
#pragma unroll
    for (int kc = 0; kc < 8; kc++)
        ldsm4(Qa[kc], smem_to_u32(KsA[0] + (wrow + arow) * KP + kc * 16 + acol));
    __syncthreads();

    auto load_kv = [&](int kt, int s) {
        uint32_t kb = smem_to_u32(KsA[s]);
        uint32_t vb = smem_to_u32(VsA[s]);
        const __half* kp = k + ((size_t)(b * TT + kt * 64)) * 512 + g * DK;
        const __half* vp = v + ((size_t)(b * TT + kt * 64)) * 512 + g * DK;
        for (int i = tid; i < 1024; i += 128) {
            int row = i >> 4, cb = (i & 15) * 16;
            uint32_t so = (uint32_t)(row * (KP * 2) + cb);
            cp16(kb + so, (const char*)(kp + (size_t)row * 512) + cb);
            cp16(vb + so, (const char*)(vp + (size_t)row * 512) + cb);
        }
        CP_COMMIT();
    };

    float Ofr[16][4];
#pragma unroll
    for (int nb = 0; nb < 16; nb++)
#pragma unroll
        for (int j = 0; j < 4; j++) Ofr[nb][j] = 0.f;

    float m0r = -1e30f, m1r = -1e30f, l0r = 0.f, l1r = 0.f;
    const int r0 = lane >> 2;
    const int c0 = (lane & 3) * 2;

    load_kv(0, 0);

    for (int kt = 0; kt <= qt; kt++) {
        const int s = kt & 1;
        if (kt < qt) {
            load_kv(kt + 1, s ^ 1);
            CP_WAIT(1);
        } else {
            CP_WAIT(0);
        }
        __syncthreads();
        const __half* Ks = KsA[s];
        const __half* Vs = VsA[s];

        // S = Q @ K^T
        float S[8][4];
#pragma unroll
        for (int nb = 0; nb < 8; nb++)
#pragma unroll
            for (int j = 0; j < 4; j++) S[nb][j] = 0.f;

#pragma unroll
        for (int kc = 0; kc < 8; kc++)
#pragma unroll
            for (int nbp = 0; nbp < 4; nbp++) {
                uint32_t bb[4];
                ldsm4(bb, smem_to_u32(Ks + (nbp * 16 + brow) * KP + kc * 16 + bcol));
                mma16816(S[2 * nbp],     Qa[kc], bb);
                mma16816(S[2 * nbp + 1], Qa[kc], bb + 2);
            }

        if (kt == qt) {
            const int rl0 = wrow + r0, rl1 = rl0 + 8;
#pragma unroll
            for (int nb = 0; nb < 8; nb++) {
                int colb = nb * 8 + c0;
                if (colb     > rl0) S[nb][0] = -1e30f;
                if (colb + 1 > rl0) S[nb][1] = -1e30f;
                if (colb     > rl1) S[nb][2] = -1e30f;
                if (colb + 1 > rl1) S[nb][3] = -1e30f;
            }
        }

        // Online softmax
        float mx0 = -1e30f, mx1 = -1e30f;
#pragma unroll
        for (int nb = 0; nb < 8; nb++) {
            mx0 = fmaxf(mx0, fmaxf(S[nb][0], S[nb][1]));
            mx1 = fmaxf(mx1, fmaxf(S[nb][2], S[nb][3]));
        }
        mx0 = fmaxf(mx0, __shfl_xor_sync(0xffffffffu, mx0, 1));
        mx0 = fmaxf(mx0, __shfl_xor_sync(0xffffffffu, mx0, 2));
        mx1 = fmaxf(mx1, __shfl_xor_sync(0xffffffffu, mx1, 1));
        mx1 = fmaxf(mx1, __shfl_xor_sync(0xffffffffu, mx1, 2));

        float mn0 = fmaxf(m0r, mx0), mn1 = fmaxf(m1r, mx1);
        float a0 = __expf(m0r - mn0), a1 = __expf(m1r - mn1);
        float s0 = 0.f, s1 = 0.f;
#pragma unroll
        for (int nb = 0; nb < 8; nb++) {
            S[nb][0] = __expf(S[nb][0] - mn0);
            S[nb][1] = __expf(S[nb][1] - mn0);
            S[nb][2] = __expf(S[nb][2] - mn1);
            S[nb][3] = __expf(S[nb][3] - mn1);
            s0 += S[nb][0] + S[nb][1];
            s1 += S[nb][2] + S[nb][3];
        }
        s0 += __shfl_xor_sync(0xffffffffu, s0, 1);
        s0 += __shfl_xor_sync(0xffffffffu, s0, 2);
        s1 += __shfl_xor_sync(0xffffffffu, s1, 1);
        s1 += __shfl_xor_sync(0xffffffffu, s1, 2);
        l0r = l0r * a0 + s0;
        l1r = l1r * a1 + s1;
        m0r = mn0; m1r = mn1;

#pragma unroll
        for (int nb = 0; nb < 16; nb++) {
            Ofr[nb][0] *= a0; Ofr[nb][1] *= a0;
            Ofr[nb][2] *= a1; Ofr[nb][3] *= a1;
        }

        uint32_t Pa[4][4];
#pragma unroll
        for (int kc = 0; kc < 4; kc++) {
            Pa[kc][0] = packh2(S[2 * kc][0],     S[2 * kc][1]);
            Pa[kc][1] = packh2(S[2 * kc][2],     S[2 * kc][3]);
            Pa[kc][2] = packh2(S[2 * kc + 1][0], S[2 * kc + 1][1]);
            Pa[kc][3] = packh2(S[2 * kc + 1][2], S[2 * kc + 1][3]);
        }

#pragma unroll
        for (int kc = 0; kc < 4; kc++)
#pragma unroll
            for (int nbp = 0; nbp < 8; nbp++) {
                uint32_t bb[4];
                ldsm4t(bb, smem_to_u32(Vs + (kc * 16 + arow) * KP + nbp * 16 + acol));
                mma16816(Ofr[2 * nbp],     Pa[kc], bb);
                mma16816(Ofr[2 * nbp + 1], Pa[kc], bb + 2);
            }
        __syncthreads();
    }

    // Epilogue: normalize, split to bf16 hi/lo, write yh/yl.
    const float i0 = 1.f / l0r, i1 = 1.f / l1r;
#pragma unroll
    for (int nb = 0; nb < 16; nb++) {
        size_t base0 = ((size_t)(b * TT + q0 + wrow + r0)) * DD + h * DK + nb * 8 + c0;
        size_t base1 = base0 + (size_t)8 * DD;
        float o00 = Ofr[nb][0] * i0, o01 = Ofr[nb][1] * i0;
        float o10 = Ofr[nb][2] * i1, o11 = Ofr[nb][3] * i1;
        __nv_bfloat16 h00, l00, h01, l01, h10, l10, h11, l11;
        split1(o00, h00, l00); split1(o01, h01, l01);
        split1(o10, h10, l10); split1(o11, h11, l11);
        __nv_bfloat162 ph0 = {h00, h01}, pl0 = {l00, l01};
        __nv_bfloat162 ph1 = {h10, h11}, pl1 = {l10, l11};
        *(__nv_bfloat162*)(yh + base0) = ph0;
        *(__nv_bfloat162*)(yl + base0) = pl0;
        *(__nv_bfloat162*)(yh + base1) = ph1;
        *(__nv_bfloat162*)(yl + base1) = pl1;
    }
}

// ---------------------------------------------------------------------------
// Launch
// ---------------------------------------------------------------------------
extern "C" void kernel_launch(void* const* d_in, const int* in_sizes, int n_in,
                              void* d_out, int out_size) {
    const float* x  = (const float*)d_in[0];
    const float* Wq = (const float*)d_in[1];
    const float* Wk = (const float*)d_in[2];
    const float* Wv = (const float*)d_in[3];
    const float* Wo = (const float*)d_in[4];
    float* out = (float*)d_out;

    float* qkv;
    __half *qh, *kh, *vh;
    __nv_bfloat16 *xh, *xl, *yh, *yl, *wth, *wtl, *woh, *wol;
    cudaGetSymbolAddress((void**)&qkv, g_qkv);
    cudaGetSymbolAddress((void**)&qh, g_qh);
    cudaGetSymbolAddress((void**)&kh, g_kh);
    cudaGetSymbolAddress((void**)&vh, g_vh);
    cudaGetSymbolAddress((void**)&xh, g_xh);
    cudaGetSymbolAddress((void**)&xl, g_xl);
    cudaGetSymbolAddress((void**)&yh, g_yh);
    cudaGetSymbolAddress((void**)&yl, g_yl);
    cudaGetSymbolAddress((void**)&wth, g_wth);
    cudaGetSymbolAddress((void**)&wtl, g_wtl);
    cudaGetSymbolAddress((void**)&woh, g_woh);
    cudaGetSymbolAddress((void**)&wol, g_wol);

    const int M = BB * TT;            // 4096
    const int nx = M * DD;

    // Prep: split x; transpose+split weights into fused [3072,2048] + Wo
    split_kernel<<<(nx + 255) / 256, 256>>>(x, xh, xl, nx);
    transpose_split<<<dim3(DD / 32, DD / 32), dim3(32, 8)>>>(Wq, wth, wtl, DD, DD);
    transpose_split<<<dim3(512 / 32, DD / 32), dim3(32, 8)>>>(
        Wk, wth + (size_t)2048 * DD, wtl + (size_t)2048 * DD, DD, 512);
    transpose_split<<<dim3(512 / 32, DD / 32), dim3(32, 8)>>>(
        Wv, wth + (size_t)2560 * DD, wtl + (size_t)2560 * DD, DD, 512);
    transpose_split<<<dim3(DD / 32, DD / 32), dim3(32, 8)>>>(Wo, woh, wol, DD, DD);

    cudaFuncSetAttribute(gemm_hl, cudaFuncAttributeMaxDynamicSharedMemorySize, GEMM_SMEM);

    // Fused QKV projection: one 768-CTA GEMM
    gemm_hl<<<dim3(3072 / GBN, M / GBM), 256, GEMM_SMEM>>>(xh, xl, wth, wtl, qkv, M, 3072, DD);

    // RoPE -> fp16 (q pre-scaled by 1/sqrt(dk)); v convert
    const float rs = 0.08838834764831845f;
    rope_h<<<(M * HH * 64 + 255) / 256, 256>>>(qkv, qh, HH, DD, rs, M * HH * 64);
    rope_h<<<(M * GG * 64 + 255) / 256, 256>>>(qkv + 2048, kh, GG, 512, 1.0f, M * GG * 64);
    conv_v<<<(M * 512 + 255) / 256, 256>>>(qkv, vh, M * 512);

    // Attention (writes bf16 hi/lo y directly)
    cudaFuncSetAttribute(attn_h, cudaFuncAttributeMaxDynamicSharedMemorySize, ATT_SMEM);
    attn_h<<<dim3(TT / 64, HH, BB), 128, ATT_SMEM>>>(qh, kh, vh, yh, yl);

    // Output projection
    gemm_hl<<<dim3(DD / GBN, M / GBM), 256, GEMM_SMEM>>>(yh, yl, woh, wol, out, M, DD, DD);
}

// round 7
// speedup vs baseline: 4.4665x; 1.3055x over previous
#include <cuda_runtime.h>
#include <cuda_bf16.h>
#include <cuda_fp16.h>
#include <mma.h>
#include <cstdint>
#include <cstddef>

using namespace nvcuda;

// Problem constants
#define BB 2
#define TT 2048
#define DD 2048
#define HH 16
#define GG 4
#define DK 128
#define RF (HH / GG)   // 4

// ---------------------------------------------------------------------------
// Scratch (__device__ globals; no allocation allowed)
// ---------------------------------------------------------------------------
__device__ __align__(16) float g_qkv[(size_t)BB * TT * 3072];      // fused QKV out
__device__ __align__(16) __half g_qh[(size_t)BB * TT * DD];
__device__ __align__(16) __half g_kh[(size_t)BB * TT * 512];
__device__ __align__(16) __half g_vh[(size_t)BB * TT * 512];
__device__ __align__(16) __half g_xh[(size_t)BB * TT * DD];        // x fp16 hi
__device__ __align__(16) __half g_xl[(size_t)BB * TT * DD];        // x fp16 lo
__device__ __align__(16) __half g_yh[(size_t)BB * TT * DD];        // attn out hi
__device__ __align__(16) __half g_yl[(size_t)BB * TT * DD];        // attn out lo
__device__ __align__(16) __half g_wt[(size_t)3072 * DD];           // [Wq;Wk;Wv]^T fp16
__device__ __align__(16) __half g_wo[(size_t)DD * DD];             // Wo^T fp16

// ---------------------------------------------------------------------------
// PTX helpers
// ---------------------------------------------------------------------------
__device__ __forceinline__ void cp16(uint32_t s, const void* g) {
    asm volatile("cp.async.cg.shared.global [%0], [%1], 16;"
                 :: "r"(s), "l"(__cvta_generic_to_global(g)));
}
#define CP_COMMIT() asm volatile("cp.async.commit_group;" ::: "memory")
#define CP_WAIT(n)  asm volatile("cp.async.wait_group %0;" :: "n"(n) : "memory")

__device__ __forceinline__ uint32_t smem_to_u32(const void* p) {
    uint32_t a;
    asm("{ .reg .u64 t; cvta.to.shared.u64 t, %1; cvt.u32.u64 %0, t; }"
        : "=r"(a) : "l"(p));
    return a;
}

__device__ __forceinline__ void mma16816(float* d, const uint32_t* a, const uint32_t* b) {
    asm volatile("mma.sync.aligned.m16n8k16.row.col.f32.f16.f16.f32 "
        "{%0,%1,%2,%3}, {%4,%5,%6,%7}, {%8,%9}, {%0,%1,%2,%3};"
        : "+f"(d[0]), "+f"(d[1]), "+f"(d[2]), "+f"(d[3])
        : "r"(a[0]), "r"(a[1]), "r"(a[2]), "r"(a[3]), "r"(b[0]), "r"(b[1]));
}
__device__ __forceinline__ void ldsm4(uint32_t* r, uint32_t addr) {
    asm volatile("ldmatrix.sync.aligned.m8n8.x4.shared.b16 {%0,%1,%2,%3}, [%4];"
        : "=r"(r[0]), "=r"(r[1]), "=r"(r[2]), "=r"(r[3]) : "r"(addr));
}
__device__ __forceinline__ void ldsm4t(uint32_t* r, uint32_t addr) {
    asm volatile("ldmatrix.sync.aligned.m8n8.x4.trans.shared.b16 {%0,%1,%2,%3}, [%4];"
        : "=r"(r[0]), "=r"(r[1]), "=r"(r[2]), "=r"(r[3]) : "r"(addr));
}
__device__ __forceinline__ uint32_t packh2(float a, float b) {
    __half2 h = __floats2half2_rn(a, b);
    return *(uint32_t*)&h;
}

// ---------------------------------------------------------------------------
// Prep kernels
// ---------------------------------------------------------------------------
__device__ __forceinline__ void split1h(float v, __half& h, __half& l) {
    __half hb = __float2half_rn(v);
    h = hb;
    l = __float2half_rn(v - __half2float(hb));
}

__global__ void split_kernel(const float* __restrict__ x,
                             __half* __restrict__ h,
                             __half* __restrict__ l, int n) {
    int i = blockIdx.x * blockDim.x + threadIdx.x;
    if (i < n) split1h(x[i], h[i], l[i]);
}

// W [Kd, Nd] row-major fp32 -> T [Nd, Kd] fp16
__global__ void transpose_h(const float* __restrict__ W,
                            __half* __restrict__ T,
                            int Kd, int Nd) {
    __shared__ float t[32][33];
    int n0 = blockIdx.x * 32, k0 = blockIdx.y * 32;
    int tx = threadIdx.x, ty = threadIdx.y;
    for (int i = ty; i < 32; i += 8)
        t[i][tx] = W[(size_t)(k0 + i) * Nd + n0 + tx];
    __syncthreads();
    for (int i = ty; i < 32; i += 8)
        T[(size_t)(n0 + i) * Kd + k0 + tx] = __float2half_rn(t[tx][i]);
}

// RoPE from fused qkv (fp32, row stride 3072) -> fp16, optional scale.
__global__ void rope_h(const float* __restrict__ src, __half* __restrict__ dst,
                       int nh, int ostride, float scale, int total) {
    int idx = blockIdx.x * blockDim.x + threadIdx.x;
    if (idx >= total) return;
    int i  = idx & 63;
    int h  = (idx >> 6) % nh;
    int bt = idx / (64 * nh);
    int t  = bt % TT;

    const float log_theta_over_64 = 0.14391156f;
    float freq = __expf(-(float)i * log_theta_over_64);
    float ang  = (float)t * freq;
    float s, c;
    sincosf(ang, &s, &c);

    size_t sbase = (size_t)bt * 3072 + h * DK;
    float x1 = src[sbase + i];
    float x2 = src[sbase + 64 + i];
    size_t obase = (size_t)bt * ostride + h * DK;
    dst[obase + i]      = __float2half((x1 * c - x2 * s) * scale);
    dst[obase + 64 + i] = __float2half((x2 * c + x1 * s) * scale);
}

// v: fp32 (qkv cols 2560:3072) -> fp16
__global__ void conv_v(const float* __restrict__ src, __half* __restrict__ dst, int total) {
    int idx = blockIdx.x * blockDim.x + threadIdx.x;
    if (idx >= total) return;
    int row = idx >> 9, col = idx & 511;
    dst[(size_t)row * 512 + col] = __float2half(src[(size_t)row * 3072 + 2560 + col]);
}

// ---------------------------------------------------------------------------
// wmma fp16 GEMM: C[M,N] = (Ah+Al)[M,K] @ B[N,K]^T, fp32 out.
// A exact (fp16 hi/lo, 2 MMAs), B single fp16 (weights).
// CTA tile 128x128x32, 256 threads = 8 warps (4m x 2n), 4-stage cp.async.
// ---------------------------------------------------------------------------
#define GBM 128
#define GBN 128
#define GBK 32
#define GLD 40
#define PLANE_B (128 * GLD * 2)          // 10240 bytes per plane
#define STAGE_B (3 * PLANE_B)            // Ah, Al, B = 30720
#define NSTAGE 4
#define GEMM_SMEM (NSTAGE * STAGE_B)     // 122880

__global__ __launch_bounds__(256) void gemm2(const __half* __restrict__ Ah,
                                             const __half* __restrict__ Al,
                                             const __half* __restrict__ B,
                                             float* __restrict__ C,
                                             int M, int N, int K) {
    extern __shared__ __align__(16) char smem[];
    const uint32_t sb = smem_to_u32(smem);
    const int tid  = threadIdx.x;
    const int warp = tid >> 5;
    const int m0 = blockIdx.y * GBM;
    const int n0 = blockIdx.x * GBN;
    const int wm = (warp >> 1) * 32;
    const int wn = (warp & 1) * 64;

    const __half* srcs[3] = {Ah + (size_t)m0 * K, Al + (size_t)m0 * K,
                             B + (size_t)n0 * K};

    auto load_stage = [&](int s, int kc) {
        uint32_t base = sb + (uint32_t)s * STAGE_B;
#pragma unroll
        for (int it = 0; it < 6; it++) {
            int id = it * 256 + tid;            // 1536 chunks
            int plane = id >> 9;
            int row   = (id >> 2) & 127;
            int c16   = (id & 3) * 16;
            uint32_t dst = base + (uint32_t)plane * PLANE_B +
                           (uint32_t)row * (GLD * 2) + c16;
            cp16(dst, srcs[plane] + (size_t)row * K + kc + (c16 >> 1));
        }
        CP_COMMIT();
    };

    wmma::fragment<wmma::accumulator, 16, 16, 16, float> acc[2][4];
#pragma unroll
    for (int i = 0; i < 2; i++)
#pragma unroll
        for (int j = 0; j < 4; j++) wmma::fill_fragment(acc[i][j], 0.f);

    const int nch = K / GBK;                 // 64
    load_stage(0, 0);
    load_stage(1, GBK);
    load_stage(2, 2 * GBK);

    for (int ch = 0; ch < nch; ch++) {
        const int s = ch & 3;
        if (ch + 3 < nch) {
            load_stage((ch + 3) & 3, (ch + 3) * GBK);
            CP_WAIT(3);
        } else if (ch + 2 < nch) {
            CP_WAIT(2);
        } else if (ch + 1 < nch) {
            CP_WAIT(1);
        } else {
            CP_WAIT(0);
        }
        __syncthreads();

        const __half* Ahs = (const __half*)(smem + s * STAGE_B);
        const __half* Als = (const __half*)(smem + s * STAGE_B + PLANE_B);
        const __half* Bs  = (const __half*)(smem + s * STAGE_B + 2 * PLANE_B);

#pragma unroll
        for (int ks = 0; ks < GBK; ks += 16) {
            wmma::fragment<wmma::matrix_a, 16, 16, 16, __half, wmma::row_major> ah[2], al[2];
#pragma unroll
            for (int i = 0; i < 2; i++) {
                wmma::load_matrix_sync(ah[i], Ahs + (wm + i * 16) * GLD + ks, GLD);
                wmma::load_matrix_sync(al[i], Als + (wm + i * 16) * GLD + ks, GLD);
            }
#pragma unroll
            for (int j = 0; j < 4; j++) {
                wmma::fragment<wmma::matrix_b, 16, 16, 16, __half, wmma::col_major> bf;
                wmma::load_matrix_sync(bf, Bs + (wn + j * 16) * GLD + ks, GLD);
#pragma unroll
                for (int i = 0; i < 2; i++) {
                    wmma::mma_sync(acc[i][j], ah[i], bf, acc[i][j]);
                    wmma::mma_sync(acc[i][j], al[i], bf, acc[i][j]);
                }
            }
        }
        __syncthreads();
    }

#pragma unroll
    for (int i = 0; i < 2; i++)
#pragma unroll
        for (int j = 0; j < 4; j++)
            wmma::store_matrix_sync(C + (size_t)(m0 + wm + i * 16) * N + n0 + wn + j * 16,
                                    acc[i][j], N, wmma::mem_row_major);
}

// ---------------------------------------------------------------------------
// Flash attention: fp16 inputs, cp.async double-buffered K/V, register O,
// epilogue writes fp16 hi/lo. 128 threads = 4 warps, BQ=BK=64.
// ---------------------------------------------------------------------------
#define KP 136
#define ATILE_H (64 * KP)
#define ATT_SMEM (4 * ATILE_H * 2)

__global__ __launch_bounds__(128, 2) void attn_h(const __half* __restrict__ q,
                                                 const __half* __restrict__ k,
                                                 const __half* __restrict__ v,
                                                 __half* __restrict__ yh,
                                                 __half* __restrict__ yl) {
    extern __shared__ __align__(16) __half asm_[];
    __half* KsA[2] = {asm_, asm_ + ATILE_H};
    __half* VsA[2] = {asm_ + 2 * ATILE_H, asm_ + 3 * ATILE_H};

    const int qt = (int)gridDim.x - 1 - (int)blockIdx.x;  // longest first
    const int h  = blockIdx.y;
    const int b  = blockIdx.z;
    const int q0 = qt * 64;
    const int g  = h / RF;

    const int tid  = threadIdx.x;
    const int lane = tid & 31;
    const int warp = tid >> 5;
    const int wrow = warp * 16;

    // Stage Q (pre-scaled in rope_h) into KsA[0].
    for (int i = tid; i < 64 * 16; i += 128) {
        int row = i >> 4, c8 = (i & 15) * 8;
        *(uint4*)(KsA[0] + row * KP + c8) =
            *(const uint4*)(q + ((size_t)(b * TT + q0 + row)) * DD + h * DK + c8);
    }
    __syncthreads();

    const int mm   = lane >> 3;
    const int arow = (mm & 1) * 8 + (lane & 7);
    const int acol = (mm >> 1) * 8;
    const int brow = (mm >> 1) * 8 + (lane & 7);
    const int bcol = (mm & 1) * 8;

    uint32_t Qa[8][4];
#pragma unroll
    for (int kc = 0; kc < 8; kc++)
        ldsm4(Qa[kc], smem_to_u32(KsA[0] + (wrow + arow) * KP + kc * 16 + acol));
    __syncthreads();

    auto load_kv = [&](int kt, int s) {
        uint32_t kb = smem_to_u32(KsA[s]);
        uint32_t vb = smem_to_u32(VsA[s]);
        const __half* kp = k + ((size_t)(b * TT + kt * 64)) * 512 + g * DK;
        const __half* vp = v + ((size_t)(b * TT + kt * 64)) * 512 + g * DK;
        for (int i = tid; i < 1024; i += 128) {
            int row = i >> 4, cb = (i & 15) * 16;
            uint32_t so = (uint32_t)(row * (KP * 2) + cb);
            cp16(kb + so, (const char*)(kp + (size_t)row * 512) + cb);
            cp16(vb + so, (const char*)(vp + (size_t)row * 512) + cb);
        }
        CP_COMMIT();
    };

    float Ofr[16][4];
#pragma unroll
    for (int nb = 0; nb < 16; nb++)
#pragma unroll
        for (int j = 0; j < 4; j++) Ofr[nb][j] = 0.f;

    float m0r = -1e30f, m1r = -1e30f, l0r = 0.f, l1r = 0.f;
    const int r0 = lane >> 2;
    const int c0 = (lane & 3) * 2;

    load_kv(0, 0);

    for (int kt = 0; kt <= qt; kt++) {
        const int s = kt & 1;
        if (kt < qt) {
            load_kv(kt + 1, s ^ 1);
            CP_WAIT(1);
        } else {
            CP_WAIT(0);
        }
        __syncthreads();
        const __half* Ks = KsA[s];
        const __half* Vs = VsA[s];

        float S[8][4];
#pragma unroll
        for (int nb = 0; nb < 8; nb++)
#pragma unroll
            for (int j = 0; j < 4; j++) S[nb][j] = 0.f;

#pragma unroll
        for (int kc = 0; kc < 8; kc++)
#pragma unroll
            for (int nbp = 0; nbp < 4; nbp++) {
                uint32_t bb[4];
                ldsm4(bb, smem_to_u32(Ks + (nbp * 16 + brow) * KP + kc * 16 + bcol));
                mma16816(S[2 * nbp],     Qa[kc], bb);
                mma16816(S[2 * nbp + 1], Qa[kc], bb + 2);
            }

        if (kt == qt) {
            const int rl0 = wrow + r0, rl1 = rl0 + 8;
#pragma unroll
            for (int nb = 0; nb < 8; nb++) {
                int colb = nb * 8 + c0;
                if (colb     > rl0) S[nb][0] = -1e30f;
                if (colb + 1 > rl0) S[nb][1] = -1e30f;
                if (colb     > rl1) S[nb][2] = -1e30f;
                if (colb + 1 > rl1) S[nb][3] = -1e30f;
            }
        }

        float mx0 = -1e30f, mx1 = -1e30f;
#pragma unroll
        for (int nb = 0; nb < 8; nb++) {
            mx0 = fmaxf(mx0, fmaxf(S[nb][0], S[nb][1]));
            mx1 = fmaxf(mx1, fmaxf(S[nb][2], S[nb][3]));
        }
        mx0 = fmaxf(mx0, __shfl_xor_sync(0xffffffffu, mx0, 1));
        mx0 = fmaxf(mx0, __shfl_xor_sync(0xffffffffu, mx0, 2));
        mx1 = fmaxf(mx1, __shfl_xor_sync(0xffffffffu, mx1, 1));
        mx1 = fmaxf(mx1, __shfl_xor_sync(0xffffffffu, mx1, 2));

        float mn0 = fmaxf(m0r, mx0), mn1 = fmaxf(m1r, mx1);
        float a0 = __expf(m0r - mn0), a1 = __expf(m1r - mn1);
        float s0 = 0.f, s1 = 0.f;
#pragma unroll
        for (int nb = 0; nb < 8; nb++) {
            S[nb][0] = __expf(S[nb][0] - mn0);
            S[nb][1] = __expf(S[nb][1] - mn0);
            S[nb][2] = __expf(S[nb][2] - mn1);
            S[nb][3] = __expf(S[nb][3] - mn1);
            s0 += S[nb][0] + S[nb][1];
            s1 += S[nb][2] + S[nb][3];
        }
        s0 += __shfl_xor_sync(0xffffffffu, s0, 1);
        s0 += __shfl_xor_sync(0xffffffffu, s0, 2);
        s1 += __shfl_xor_sync(0xffffffffu, s1, 1);
        s1 += __shfl_xor_sync(0xffffffffu, s1, 2);
        l0r = l0r * a0 + s0;
        l1r = l1r * a1 + s1;
        m0r = mn0; m1r = mn1;

#pragma unroll
        for (int nb = 0; nb < 16; nb++) {
            Ofr[nb][0] *= a0; Ofr[nb][1] *= a0;
            Ofr[nb][2] *= a1; Ofr[nb][3] *= a1;
        }

        uint32_t Pa[4][4];
#pragma unroll
        for (int kc = 0; kc < 4; kc++) {
            Pa[kc][0] = packh2(S[2 * kc][0],     S[2 * kc][1]);
            Pa[kc][1] = packh2(S[2 * kc][2],     S[2 * kc][3]);
            Pa[kc][2] = packh2(S[2 * kc + 1][0], S[2 * kc + 1][1]);
            Pa[kc][3] = packh2(S[2 * kc + 1][2], S[2 * kc + 1][3]);
        }

#pragma unroll
        for (int kc = 0; kc < 4; kc++)
#pragma unroll
            for (int nbp = 0; nbp < 8; nbp++) {
                uint32_t bb[4];
                ldsm4t(bb, smem_to_u32(Vs + (kc * 16 + arow) * KP + nbp * 16 + acol));
                mma16816(Ofr[2 * nbp],     Pa[kc], bb);
                mma16816(Ofr[2 * nbp + 1], Pa[kc], bb + 2);
            }
        __syncthreads();
    }

    // Epilogue: normalize, split to fp16 hi/lo, write yh/yl.
    const float i0 = 1.f / l0r, i1 = 1.f / l1r;
#pragma unroll
    for (int nb = 0; nb < 16; nb++) {
        size_t base0 = ((size_t)(b * TT + q0 + wrow + r0)) * DD + h * DK + nb * 8 + c0;
        size_t base1 = base0 + (size_t)8 * DD;
        float o00 = Ofr[nb][0] * i0, o01 = Ofr[nb][1] * i0;
        float o10 = Ofr[nb][2] * i1, o11 = Ofr[nb][3] * i1;
        __half h00, l00, h01, l01, h10, l10, h11, l11;
        split1h(o00, h00, l00); split1h(o01, h01, l01);
        split1h(o10, h10, l10); split1h(o11, h11, l11);
        __half2 ph0 = {h00, h01}, pl0 = {l00, l01};
        __half2 ph1 = {h10, h11}, pl1 = {l10, l11};
        *(__half2*)(yh + base0) = ph0;
        *(__half2*)(yl + base0) = pl0;
        *(__half2*)(yh + base1) = ph1;
        *(__half2*)(yl + base1) = pl1;
    }
}

// ---------------------------------------------------------------------------
// Launch
// ---------------------------------------------------------------------------
extern "C" void kernel_launch(void* const* d_in, const int* in_sizes, int n_in,
                              void* d_out, int out_size) {
    const float* x  = (const float*)d_in[0];
    const float* Wq = (const float*)d_in[1];
    const float* Wk = (const float*)d_in[2];
    const float* Wv = (const float*)d_in[3];
    const float* Wo = (const float*)d_in[4];
    float* out = (float*)d_out;

    float* qkv;
    __half *qh, *kh, *vh, *xh, *xl, *yh, *yl, *wt, *wo;
    cudaGetSymbolAddress((void**)&qkv, g_qkv);
    cudaGetSymbolAddress((void**)&qh, g_qh);
    cudaGetSymbolAddress((void**)&kh, g_kh);
    cudaGetSymbolAddress((void**)&vh, g_vh);
    cudaGetSymbolAddress((void**)&xh, g_xh);
    cudaGetSymbolAddress((void**)&xl, g_xl);
    cudaGetSymbolAddress((void**)&yh, g_yh);
    cudaGetSymbolAddress((void**)&yl, g_yl);
    cudaGetSymbolAddress((void**)&wt, g_wt);
    cudaGetSymbolAddress((void**)&wo, g_wo);

    const int M = BB * TT;            // 4096
    const int nx = M * DD;

    // Prep: split x (fp16 hi/lo); transpose weights to fp16 [N,K]
    split_kernel<<<(nx + 255) / 256, 256>>>(x, xh, xl, nx);
    transpose_h<<<dim3(DD / 32, DD / 32), dim3(32, 8)>>>(Wq, wt, DD, DD);
    transpose_h<<<dim3(512 / 32, DD / 32), dim3(32, 8)>>>(
        Wk, wt + (size_t)2048 * DD, DD, 512);
    transpose_h<<<dim3(512 / 32, DD / 32), dim3(32, 8)>>>(
        Wv, wt + (size_t)2560 * DD, DD, 512);
    transpose_h<<<dim3(DD / 32, DD / 32), dim3(32, 8)>>>(Wo, wo, DD, DD);

    cudaFuncSetAttribute(gemm2, cudaFuncAttributeMaxDynamicSharedMemorySize, GEMM_SMEM);

    // Fused QKV projection
    gemm2<<<dim3(3072 / GBN, M / GBM), 256, GEMM_SMEM>>>(xh, xl, wt, qkv, M, 3072, DD);

    // RoPE -> fp16 (q pre-scaled by 1/sqrt(dk)); v convert
    const float rs = 0.08838834764831845f;
    rope_h<<<(M * HH * 64 + 255) / 256, 256>>>(qkv, qh, HH, DD, rs, M * HH * 64);
    rope_h<<<(M * GG * 64 + 255) / 256, 256>>>(qkv + 2048, kh, GG, 512, 1.0f, M * GG * 64);
    conv_v<<<(M * 512 + 255) / 256, 256>>>(qkv, vh, M * 512);

    // Attention (writes fp16 hi/lo y directly)
    cudaFuncSetAttribute(attn_h, cudaFuncAttributeMaxDynamicSharedMemorySize, ATT_SMEM);
    attn_h<<<dim3(TT / 64, HH, BB), 128, ATT_SMEM>>>(qh, kh, vh, yh, yl);

    // Output projection
    gemm2<<<dim3(DD / GBN, M / GBM), 256, GEMM_SMEM>>>(yh, yl, wo, out, M, DD, DD);
}

// round 8
// speedup vs baseline: 6.4548x; 1.4452x over previous
#include <cuda_runtime.h>
#include <cuda_bf16.h>
#include <cuda_fp16.h>
#include <mma.h>
#include <cstdint>
#include <cstddef>

using namespace nvcuda;

// Problem constants
#define BB 2
#define TT 2048
#define DD 2048
#define HH 16
#define GG 4
#define DK 128
#define RF (HH / GG)   // 4

// ---------------------------------------------------------------------------
// Scratch (__device__ globals; no allocation allowed)
// ---------------------------------------------------------------------------
__device__ __align__(16) float g_qkv[(size_t)BB * TT * 3072];      // fused QKV out
__device__ __align__(16) __half g_qh[(size_t)BB * TT * DD];
__device__ __align__(16) __half g_kh[(size_t)BB * TT * 512];
__device__ __align__(16) __half g_vh[(size_t)BB * TT * 512];
__device__ __align__(16) __half g_xh[(size_t)BB * TT * DD];        // x fp16
__device__ __align__(16) __half g_yh[(size_t)BB * TT * DD];        // attn out fp16
__device__ __align__(16) __half g_wt[(size_t)3072 * DD];           // [Wq;Wk;Wv]^T fp16
__device__ __align__(16) __half g_wo[(size_t)DD * DD];             // Wo^T fp16

// ---------------------------------------------------------------------------
// PTX helpers
// ---------------------------------------------------------------------------
__device__ __forceinline__ void cp16(uint32_t s, const void* g) {
    asm volatile("cp.async.cg.shared.global [%0], [%1], 16;"
                 :: "r"(s), "l"(__cvta_generic_to_global(g)));
}
#define CP_COMMIT() asm volatile("cp.async.commit_group;" ::: "memory")
#define CP_WAIT(n)  asm volatile("cp.async.wait_group %0;" :: "n"(n) : "memory")

__device__ __forceinline__ uint32_t smem_to_u32(const void* p) {
    uint32_t a;
    asm("{ .reg .u64 t; cvta.to.shared.u64 t, %1; cvt.u32.u64 %0, t; }"
        : "=r"(a) : "l"(p));
    return a;
}

__device__ __forceinline__ void mma16816(float* d, const uint32_t* a, const uint32_t* b) {
    asm volatile("mma.sync.aligned.m16n8k16.row.col.f32.f16.f16.f32 "
        "{%0,%1,%2,%3}, {%4,%5,%6,%7}, {%8,%9}, {%0,%1,%2,%3};"
        : "+f"(d[0]), "+f"(d[1]), "+f"(d[2]), "+f"(d[3])
        : "r"(a[0]), "r"(a[1]), "r"(a[2]), "r"(a[3]), "r"(b[0]), "r"(b[1]));
}
__device__ __forceinline__ void ldsm4(uint32_t* r, uint32_t addr) {
    asm volatile("ldmatrix.sync.aligned.m8n8.x4.shared.b16 {%0,%1,%2,%3}, [%4];"
        : "=r"(r[0]), "=r"(r[1]), "=r"(r[2]), "=r"(r[3]) : "r"(addr));
}
__device__ __forceinline__ void ldsm4t(uint32_t* r, uint32_t addr) {
    asm volatile("ldmatrix.sync.aligned.m8n8.x4.trans.shared.b16 {%0,%1,%2,%3}, [%4];"
        : "=r"(r[0]), "=r"(r[1]), "=r"(r[2]), "=r"(r[3]) : "r"(addr));
}
__device__ __forceinline__ uint32_t packh2(float a, float b) {
    __half2 h = __floats2half2_rn(a, b);
    return *(uint32_t*)&h;
}

// ---------------------------------------------------------------------------
// Prep kernels
// ---------------------------------------------------------------------------
__global__ void conv_x(const float* __restrict__ x, __half* __restrict__ h, int n) {
    int i = blockIdx.x * blockDim.x + threadIdx.x;
    if (i < n) h[i] = __float2half_rn(x[i]);
}

// W [Kd, Nd] row-major fp32 -> T [Nd, Kd] fp16
__global__ void transpose_h(const float* __restrict__ W,
                            __half* __restrict__ T,
                            int Kd, int Nd) {
    __shared__ float t[32][33];
    int n0 = blockIdx.x * 32, k0 = blockIdx.y * 32;
    int tx = threadIdx.x, ty = threadIdx.y;
    for (int i = ty; i < 32; i += 8)
        t[i][tx] = W[(size_t)(k0 + i) * Nd + n0 + tx];
    __syncthreads();
    for (int i = ty; i < 32; i += 8)
        T[(size_t)(n0 + i) * Kd + k0 + tx] = __float2half_rn(t[tx][i]);
}

// RoPE from fused qkv (fp32, row stride 3072) -> fp16, optional scale.
__global__ void rope_h(const float* __restrict__ src, __half* __restrict__ dst,
                       int nh, int ostride, float scale, int total) {
    int idx = blockIdx.x * blockDim.x + threadIdx.x;
    if (idx >= total) return;
    int i  = idx & 63;
    int h  = (idx >> 6) % nh;
    int bt = idx / (64 * nh);
    int t  = bt % TT;

    const float log_theta_over_64 = 0.14391156f;
    float freq = __expf(-(float)i * log_theta_over_64);
    float ang  = (float)t * freq;
    float s, c;
    sincosf(ang, &s, &c);

    size_t sbase = (size_t)bt * 3072 + h * DK;
    float x1 = src[sbase + i];
    float x2 = src[sbase + 64 + i];
    size_t obase = (size_t)bt * ostride + h * DK;
    dst[obase + i]      = __float2half((x1 * c - x2 * s) * scale);
    dst[obase + 64 + i] = __float2half((x2 * c + x1 * s) * scale);
}

// v: fp32 (qkv cols 2560:3072) -> fp16
__global__ void conv_v(const float* __restrict__ src, __half* __restrict__ dst, int total) {
    int idx = blockIdx.x * blockDim.x + threadIdx.x;
    if (idx >= total) return;
    int row = idx >> 9, col = idx & 511;
    dst[(size_t)row * 512 + col] = __float2half(src[(size_t)row * 3072 + 2560 + col]);
}

// ---------------------------------------------------------------------------
// wmma fp16 GEMM: C[M,N] = A[M,K] @ B[N,K]^T, fp32 out.
// CTA tile 128x256x32, 512 threads = 16 warps (4m x 4n), warp tile 32x64.
// 4-stage cp.async pipeline.
// ---------------------------------------------------------------------------
#define GBM 128
#define GBN 256
#define GBK 32
#define GLD 40
#define APLANE_B (128 * GLD * 2)         // 10240
#define BPLANE_B (256 * GLD * 2)         // 20480
#define STAGE_B (APLANE_B + BPLANE_B)    // 30720
#define NSTAGE 4
#define GEMM_SMEM (NSTAGE * STAGE_B)     // 122880

__global__ __launch_bounds__(512) void gemm1(const __half* __restrict__ A,
                                             const __half* __restrict__ B,
                                             float* __restrict__ C,
                                             int M, int N, int K) {
    extern __shared__ __align__(16) char smem[];
    const uint32_t sb = smem_to_u32(smem);
    const int tid  = threadIdx.x;
    const int warp = tid >> 5;
    const int m0 = blockIdx.y * GBM;
    const int n0 = blockIdx.x * GBN;
    const int wm = (warp & 3) * 32;
    const int wn = (warp >> 2) * 64;

    const __half* Ap = A + (size_t)m0 * K;
    const __half* Bp = B + (size_t)n0 * K;

    // 1536 chunks per stage (A: 512, B: 1024); 3 per thread
    auto load_stage = [&](int s, int kc) {
        uint32_t base = sb + (uint32_t)s * STAGE_B;
#pragma unroll
        for (int it = 0; it < 3; it++) {
            int id = it * 512 + tid;
            if (id < 512) {
                int row = id >> 2, c16 = (id & 3) * 16;
                cp16(base + (uint32_t)row * (GLD * 2) + c16,
                     Ap + (size_t)row * K + kc + (c16 >> 1));
            } else {
                int id2 = id - 512;
                int row = id2 >> 2, c16 = (id2 & 3) * 16;
                cp16(base + APLANE_B + (uint32_t)row * (GLD * 2) + c16,
                     Bp + (size_t)row * K + kc + (c16 >> 1));
            }
        }
        CP_COMMIT();
    };

    wmma::fragment<wmma::accumulator, 16, 16, 16, float> acc[2][4];
#pragma unroll
    for (int i = 0; i < 2; i++)
#pragma unroll
        for (int j = 0; j < 4; j++) wmma::fill_fragment(acc[i][j], 0.f);

    const int nch = K / GBK;                 // 64
    load_stage(0, 0);
    load_stage(1, GBK);
    load_stage(2, 2 * GBK);

    for (int ch = 0; ch < nch; ch++) {
        const int s = ch & 3;
        if (ch + 3 < nch) {
            load_stage((ch + 3) & 3, (ch + 3) * GBK);
            CP_WAIT(3);
        } else if (ch + 2 < nch) {
            CP_WAIT(2);
        } else if (ch + 1 < nch) {
            CP_WAIT(1);
        } else {
            CP_WAIT(0);
        }
        __syncthreads();

        const __half* As = (const __half*)(smem + s * STAGE_B);
        const __half* Bs = (const __half*)(smem + s * STAGE_B + APLANE_B);

#pragma unroll
        for (int ks = 0; ks < GBK; ks += 16) {
            wmma::fragment<wmma::matrix_a, 16, 16, 16, __half, wmma::row_major> af[2];
#pragma unroll
            for (int i = 0; i < 2; i++)
                wmma::load_matrix_sync(af[i], As + (wm + i * 16) * GLD + ks, GLD);
#pragma unroll
            for (int j = 0; j < 4; j++) {
                wmma::fragment<wmma::matrix_b, 16, 16, 16, __half, wmma::col_major> bf;
                wmma::load_matrix_sync(bf, Bs + (wn + j * 16) * GLD + ks, GLD);
#pragma unroll
                for (int i = 0; i < 2; i++)
                    wmma::mma_sync(acc[i][j], af[i], bf, acc[i][j]);
            }
        }
        __syncthreads();
    }

#pragma unroll
    for (int i = 0; i < 2; i++)
#pragma unroll
        for (int j = 0; j < 4; j++)
            wmma::store_matrix_sync(C + (size_t)(m0 + wm + i * 16) * N + n0 + wn + j * 16,
                                    acc[i][j], N, wmma::mem_row_major);
}

// ---------------------------------------------------------------------------
// Flash attention: fp16 inputs, cp.async double-buffered K/V, register O,
// epilogue writes fp16. 128 threads = 4 warps, BQ=BK=64.
// ---------------------------------------------------------------------------
#define KP 136
#define ATILE_H (64 * KP)
#define ATT_SMEM (4 * ATILE_H * 2)

__global__ __launch_bounds__(128, 2) void attn_h(const __half* __restrict__ q,
                                                 const __half* __restrict__ k,
                                                 const __half* __restrict__ v,
                                                 __half* __restrict__ yh) {
    extern __shared__ __align__(16) __half asm_[];
    __half* KsA[2] = {asm_, asm_ + ATILE_H};
    __half* VsA[2] = {asm_ + 2 * ATILE_H, asm_ + 3 * ATILE_H};

    const int qt = (int)gridDim.x - 1 - (int)blockIdx.x;  // longest first
    const int h  = blockIdx.y;
    const int b  = blockIdx.z;
    const int q0 = qt * 64;
    const int g  = h / RF;

    const int tid  = threadIdx.x;
    const int lane = tid & 31;
    const int warp = tid >> 5;
    const int wrow = warp * 16;

    // Stage Q (pre-scaled in rope_h) into KsA[0].
    for (int i = tid; i < 64 * 16; i += 128) {
        int row = i >> 4, c8 = (i & 15) * 8;
        *(uint4*)(KsA[0] + row * KP + c8) =
            *(const uint4*)(q + ((size_t)(b * TT + q0 + row)) * DD + h * DK + c8);
    }
    __syncthreads();

    const int mm   = lane >> 3;
    const int arow = (mm & 1) * 8 + (lane & 7);
    const int acol = (mm >> 1) * 8;
    const int brow = (mm >> 1) * 8 + (lane & 7);
    const int bcol = (mm & 1) * 8;

    uint32_t Qa[8][4];
#pragma unroll
    for (int kc = 0; kc < 8; kc++)
        ldsm4(Qa[kc], smem_to_u32(KsA[0] + (wrow + arow) * KP + kc * 16 + acol));
    __syncthreads();

    auto load_kv = [&](int kt, int s) {
        uint32_t kb = smem_to_u32(KsA[s]);
        uint32_t vb = smem_to_u32(VsA[s]);
        const __half* kp = k + ((size_t)(b * TT + kt * 64)) * 512 + g * DK;
        const __half* vp = v + ((size_t)(b * TT + kt * 64)) * 512 + g * DK;
        for (int i = tid; i < 1024; i += 128) {
            int row = i >> 4, cb = (i & 15) * 16;
            uint32_t so = (uint32_t)(row * (KP * 2) + cb);
            cp16(kb + so, (const char*)(kp + (size_t)row * 512) + cb);
            cp16(vb + so, (const char*)(vp + (size_t)row * 512) + cb);
        }
        CP_COMMIT();
    };

    float Ofr[16][4];
#pragma unroll
    for (int nb = 0; nb < 16; nb++)
#pragma unroll
        for (int j = 0; j < 4; j++) Ofr[nb][j] = 0.f;

    float m0r = -1e30f, m1r = -1e30f, l0r = 0.f, l1r = 0.f;
    const int r0 = lane >> 2;
    const int c0 = (lane & 3) * 2;

    load_kv(0, 0);

    for (int kt = 0; kt <= qt; kt++) {
        const int s = kt & 1;
        if (kt < qt) {
            load_kv(kt + 1, s ^ 1);
            CP_WAIT(1);
        } else {
            CP_WAIT(0);
        }
        __syncthreads();
        const __half* Ks = KsA[s];
        const __half* Vs = VsA[s];

        float S[8][4];
#pragma unroll
        for (int nb = 0; nb < 8; nb++)
#pragma unroll
            for (int j = 0; j < 4; j++) S[nb][j] = 0.f;

#pragma unroll
        for (int kc = 0; kc < 8; kc++)
#pragma unroll
            for (int nbp = 0; nbp < 4; nbp++) {
                uint32_t bb[4];
                ldsm4(bb, smem_to_u32(Ks + (nbp * 16 + brow) * KP + kc * 16 + bcol));
                mma16816(S[2 * nbp],     Qa[kc], bb);
                mma16816(S[2 * nbp + 1], Qa[kc], bb + 2);
            }

        if (kt == qt) {
            const int rl0 = wrow + r0, rl1 = rl0 + 8;
#pragma unroll
            for (int nb = 0; nb < 8; nb++) {
                int colb = nb * 8 + c0;
                if (colb     > rl0) S[nb][0] = -1e30f;
                if (colb + 1 > rl0) S[nb][1] = -1e30f;
                if (colb     > rl1) S[nb][2] = -1e30f;
                if (colb + 1 > rl1) S[nb][3] = -1e30f;
            }
        }

        float mx0 = -1e30f, mx1 = -1e30f;
#pragma unroll
        for (int nb = 0; nb < 8; nb++) {
            mx0 = fmaxf(mx0, fmaxf(S[nb][0], S[nb][1]));
            mx1 = fmaxf(mx1, fmaxf(S[nb][2], S[nb][3]));
        }
        mx0 = fmaxf(mx0, __shfl_xor_sync(0xffffffffu, mx0, 1));
        mx0 = fmaxf(mx0, __shfl_xor_sync(0xffffffffu, mx0, 2));
        mx1 = fmaxf(mx1, __shfl_xor_sync(0xffffffffu, mx1, 1));
        mx1 = fmaxf(mx1, __shfl_xor_sync(0xffffffffu, mx1, 2));

        float mn0 = fmaxf(m0r, mx0), mn1 = fmaxf(m1r, mx1);
        float a0 = __expf(m0r - mn0), a1 = __expf(m1r - mn1);
        float s0 = 0.f, s1 = 0.f;
#pragma unroll
        for (int nb = 0; nb < 8; nb++) {
            S[nb][0] = __expf(S[nb][0] - mn0);
            S[nb][1] = __expf(S[nb][1] - mn0);
            S[nb][2] = __expf(S[nb][2] - mn1);
            S[nb][3] = __expf(S[nb][3] - mn1);
            s0 += S[nb][0] + S[nb][1];
            s1 += S[nb][2] + S[nb][3];
        }
        s0 += __shfl_xor_sync(0xffffffffu, s0, 1);
        s0 += __shfl_xor_sync(0xffffffffu, s0, 2);
        s1 += __shfl_xor_sync(0xffffffffu, s1, 1);
        s1 += __shfl_xor_sync(0xffffffffu, s1, 2);
        l0r = l0r * a0 + s0;
        l1r = l1r * a1 + s1;
        m0r = mn0; m1r = mn1;

#pragma unroll
        for (int nb = 0; nb < 16; nb++) {
            Ofr[nb][0] *= a0; Ofr[nb][1] *= a0;
            Ofr[nb][2] *= a1; Ofr[nb][3] *= a1;
        }

        uint32_t Pa[4][4];
#pragma unroll
        for (int kc = 0; kc < 4; kc++) {
            Pa[kc][0] = packh2(S[2 * kc][0],     S[2 * kc][1]);
            Pa[kc][1] = packh2(S[2 * kc][2],     S[2 * kc][3]);
            Pa[kc][2] = packh2(S[2 * kc + 1][0], S[2 * kc + 1][1]);
            Pa[kc][3] = packh2(S[2 * kc + 1][2], S[2 * kc + 1][3]);
        }

#pragma unroll
        for (int kc = 0; kc < 4; kc++)
#pragma unroll
            for (int nbp = 0; nbp < 8; nbp++) {
                uint32_t bb[4];
                ldsm4t(bb, smem_to_u32(Vs + (kc * 16 + arow) * KP + nbp * 16 + acol));
                mma16816(Ofr[2 * nbp],     Pa[kc], bb);
                mma16816(Ofr[2 * nbp + 1], Pa[kc], bb + 2);
            }
        __syncthreads();
    }

    // Epilogue: normalize, write fp16 y.
    const float i0 = 1.f / l0r, i1 = 1.f / l1r;
#pragma unroll
    for (int nb = 0; nb < 16; nb++) {
        size_t base0 = ((size_t)(b * TT + q0 + wrow + r0)) * DD + h * DK + nb * 8 + c0;
        size_t base1 = base0 + (size_t)8 * DD;
        *(__half2*)(yh + base0) = __floats2half2_rn(Ofr[nb][0] * i0, Ofr[nb][1] * i0);
        *(__half2*)(yh + base1) = __floats2half2_rn(Ofr[nb][2] * i1, Ofr[nb][3] * i1);
    }
}

// ---------------------------------------------------------------------------
// Launch
// ---------------------------------------------------------------------------
extern "C" void kernel_launch(void* const* d_in, const int* in_sizes, int n_in,
                              void* d_out, int out_size) {
    const float* x  = (const float*)d_in[0];
    const float* Wq = (const float*)d_in[1];
    const float* Wk = (const float*)d_in[2];
    const float* Wv = (const float*)d_in[3];
    const float* Wo = (const float*)d_in[4];
    float* out = (float*)d_out;

    float* qkv;
    __half *qh, *kh, *vh, *xh, *yh, *wt, *wo;
    cudaGetSymbolAddress((void**)&qkv, g_qkv);
    cudaGetSymbolAddress((void**)&qh, g_qh);
    cudaGetSymbolAddress((void**)&kh, g_kh);
    cudaGetSymbolAddress((void**)&vh, g_vh);
    cudaGetSymbolAddress((void**)&xh, g_xh);
    cudaGetSymbolAddress((void**)&yh, g_yh);
    cudaGetSymbolAddress((void**)&wt, g_wt);
    cudaGetSymbolAddress((void**)&wo, g_wo);

    const int M = BB * TT;            // 4096
    const int nx = M * DD;

    // Prep: x -> fp16; transpose weights to fp16 [N,K]
    conv_x<<<(nx + 255) / 256, 256>>>(x, xh, nx);
    transpose_h<<<dim3(DD / 32, DD / 32), dim3(32, 8)>>>(Wq, wt, DD, DD);
    transpose_h<<<dim3(512 / 32, DD / 32), dim3(32, 8)>>>(
        Wk, wt + (size_t)2048 * DD, DD, 512);
    transpose_h<<<dim3(512 / 32, DD / 32), dim3(32, 8)>>>(
        Wv, wt + (size_t)2560 * DD, DD, 512);
    transpose_h<<<dim3(DD / 32, DD / 32), dim3(32, 8)>>>(Wo, wo, DD, DD);

    cudaFuncSetAttribute(gemm1, cudaFuncAttributeMaxDynamicSharedMemorySize, GEMM_SMEM);

    // Fused QKV projection
    gemm1<<<dim3(3072 / GBN, M / GBM), 512, GEMM_SMEM>>>(xh, wt, qkv, M, 3072, DD);

    // RoPE -> fp16 (q pre-scaled by 1/sqrt(dk)); v convert
    const float rs = 0.08838834764831845f;
    rope_h<<<(M * HH * 64 + 255) / 256, 256>>>(qkv, qh, HH, DD, rs, M * HH * 64);
    rope_h<<<(M * GG * 64 + 255) / 256, 256>>>(qkv + 2048, kh, GG, 512, 1.0f, M * GG * 64);
    conv_v<<<(M * 512 + 255) / 256, 256>>>(qkv, vh, M * 512);

    // Attention
    cudaFuncSetAttribute(attn_h, cudaFuncAttributeMaxDynamicSharedMemorySize, ATT_SMEM);
    attn_h<<<dim3(TT / 64, HH, BB), 128, ATT_SMEM>>>(qh, kh, vh, yh);

    // Output projection
    gemm1<<<dim3(DD / GBN, M / GBM), 512, GEMM_SMEM>>>(yh, wo, out, M, DD, DD);
}

// round 9
// speedup vs baseline: 6.7885x; 1.0517x over previous
#include <cuda_runtime.h>
#include <cuda_bf16.h>
#include <cuda_fp16.h>
#include <cstdint>
#include <cstddef>

// Problem constants
#define BB 2
#define TT 2048
#define DD 2048
#define HH 16
#define GG 4
#define DK 128
#define RF (HH / GG)   // 4

// ---------------------------------------------------------------------------
// Scratch (__device__ globals; no allocation allowed)
// ---------------------------------------------------------------------------
__device__ __align__(16) __half g_qkv[(size_t)BB * TT * 3072];     // fused QKV out (fp16)
__device__ __align__(16) __half g_qh[(size_t)BB * TT * DD];
__device__ __align__(16) __half g_kh[(size_t)BB * TT * 512];
__device__ __align__(16) __half g_xh[(size_t)BB * TT * DD];        // x fp16
__device__ __align__(16) __half g_yh[(size_t)BB * TT * DD];        // attn out fp16
__device__ __align__(16) __half g_wt[(size_t)3072 * DD];           // [Wq;Wk;Wv]^T fp16
__device__ __align__(16) __half g_wo[(size_t)DD * DD];             // Wo^T fp16

// ---------------------------------------------------------------------------
// PTX helpers
// ---------------------------------------------------------------------------
__device__ __forceinline__ void cp16(uint32_t s, const void* g) {
    asm volatile("cp.async.cg.shared.global [%0], [%1], 16;"
                 :: "r"(s), "l"(__cvta_generic_to_global(g)));
}
#define CP_COMMIT() asm volatile("cp.async.commit_group;" ::: "memory")
#define CP_WAIT(n)  asm volatile("cp.async.wait_group %0;" :: "n"(n) : "memory")

__device__ __forceinline__ uint32_t smem_to_u32(const void* p) {
    uint32_t a;
    asm("{ .reg .u64 t; cvta.to.shared.u64 t, %1; cvt.u32.u64 %0, t; }"
        : "=r"(a) : "l"(p));
    return a;
}

__device__ __forceinline__ void mma16816(float* d, const uint32_t* a, const uint32_t* b) {
    asm volatile("mma.sync.aligned.m16n8k16.row.col.f32.f16.f16.f32 "
        "{%0,%1,%2,%3}, {%4,%5,%6,%7}, {%8,%9}, {%0,%1,%2,%3};"
        : "+f"(d[0]), "+f"(d[1]), "+f"(d[2]), "+f"(d[3])
        : "r"(a[0]), "r"(a[1]), "r"(a[2]), "r"(a[3]), "r"(b[0]), "r"(b[1]));
}
__device__ __forceinline__ void ldsm4(uint32_t* r, uint32_t addr) {
    asm volatile("ldmatrix.sync.aligned.m8n8.x4.shared.b16 {%0,%1,%2,%3}, [%4];"
        : "=r"(r[0]), "=r"(r[1]), "=r"(r[2]), "=r"(r[3]) : "r"(addr));
}
__device__ __forceinline__ void ldsm4t(uint32_t* r, uint32_t addr) {
    asm volatile("ldmatrix.sync.aligned.m8n8.x4.trans.shared.b16 {%0,%1,%2,%3}, [%4];"
        : "=r"(r[0]), "=r"(r[1]), "=r"(r[2]), "=r"(r[3]) : "r"(addr));
}
__device__ __forceinline__ uint32_t packh2(float a, float b) {
    __half2 h = __floats2half2_rn(a, b);
    return *(uint32_t*)&h;
}

// typed pair store for GEMM epilogue
__device__ __forceinline__ void store2(__half* p, float a, float b) {
    *(__half2*)p = __floats2half2_rn(a, b);
}
__device__ __forceinline__ void store2(float* p, float a, float b) {
    *(float2*)p = make_float2(a, b);
}

// ---------------------------------------------------------------------------
// Prep kernels
// ---------------------------------------------------------------------------
__global__ void conv_x(const float* __restrict__ x, __half* __restrict__ h, int n) {
    int i = blockIdx.x * blockDim.x + threadIdx.x;
    if (i < n) h[i] = __float2half_rn(x[i]);
}

// W [Kd, Nd] row-major fp32 -> T [Nd, Kd] fp16
__global__ void transpose_h(const float* __restrict__ W,
                            __half* __restrict__ T,
                            int Kd, int Nd) {
    __shared__ float t[32][33];
    int n0 = blockIdx.x * 32, k0 = blockIdx.y * 32;
    int tx = threadIdx.x, ty = threadIdx.y;
    for (int i = ty; i < 32; i += 8)
        t[i][tx] = W[(size_t)(k0 + i) * Nd + n0 + tx];
    __syncthreads();
    for (int i = ty; i < 32; i += 8)
        T[(size_t)(n0 + i) * Kd + k0 + tx] = __float2half_rn(t[tx][i]);
}

// RoPE from fused qkv (fp16, row stride 3072) -> fp16, optional scale.
__global__ void rope_h(const __half* __restrict__ src, __half* __restrict__ dst,
                       int nh, int ostride, float scale, int total) {
    int idx = blockIdx.x * blockDim.x + threadIdx.x;
    if (idx >= total) return;
    int i  = idx & 63;
    int h  = (idx >> 6) % nh;
    int bt = idx / (64 * nh);
    int t  = bt % TT;

    const float log_theta_over_64 = 0.14391156f;
    float freq = __expf(-(float)i * log_theta_over_64);
    float ang  = (float)t * freq;
    float s, c;
    sincosf(ang, &s, &c);

    size_t sbase = (size_t)bt * 3072 + h * DK;
    float x1 = __half2float(src[sbase + i]);
    float x2 = __half2float(src[sbase + 64 + i]);
    size_t obase = (size_t)bt * ostride + h * DK;
    dst[obase + i]      = __float2half((x1 * c - x2 * s) * scale);
    dst[obase + 64 + i] = __float2half((x2 * c + x1 * s) * scale);
}

// ---------------------------------------------------------------------------
// Raw-mma fp16 GEMM: C[M,N] = A[M,K] @ B[N,K]^T, OutT out (fp16 or fp32).
// CTA tile 128x256x32, 512 threads = 16 warps (4m x 4n), warp tile 32x64.
// 4-stage cp.async pipeline; ldmatrix fragments, A reused across 4 B tiles.
// ---------------------------------------------------------------------------
#define GBM 128
#define GBN 256
#define GBK 32
#define GLD 40
#define APLANE_B (128 * GLD * 2)         // 10240
#define BPLANE_B (256 * GLD * 2)         // 20480
#define STAGE_B (APLANE_B + BPLANE_B)    // 30720
#define NSTAGE 4
#define GEMM_SMEM (NSTAGE * STAGE_B)     // 122880

template <typename OutT>
__global__ __launch_bounds__(512) void gemm_mma(const __half* __restrict__ A,
                                                const __half* __restrict__ B,
                                                OutT* __restrict__ C,
                                                int M, int N, int K) {
    extern __shared__ __align__(16) char smem[];
    const uint32_t sb = smem_to_u32(smem);
    const int tid  = threadIdx.x;
    const int lane = tid & 31;
    const int warp = tid >> 5;
    const int m0 = blockIdx.y * GBM;
    const int n0 = blockIdx.x * GBN;
    const int wm = (warp & 3) * 32;
    const int wn = (warp >> 2) * 64;

    const __half* Ap = A + (size_t)m0 * K;
    const __half* Bp = B + (size_t)n0 * K;

    // 1536 chunks per stage (A: 512, B: 1024); 3 per thread
    auto load_stage = [&](int s, int kc) {
        uint32_t base = sb + (uint32_t)s * STAGE_B;
#pragma unroll
        for (int it = 0; it < 3; it++) {
            int id = it * 512 + tid;
            if (id < 512) {
                int row = id >> 2, c16 = (id & 3) * 16;
                cp16(base + (uint32_t)row * (GLD * 2) + c16,
                     Ap + (size_t)row * K + kc + (c16 >> 1));
            } else {
                int id2 = id - 512;
                int row = id2 >> 2, c16 = (id2 & 3) * 16;
                cp16(base + APLANE_B + (uint32_t)row * (GLD * 2) + c16,
                     Bp + (size_t)row * K + kc + (c16 >> 1));
            }
        }
        CP_COMMIT();
    };

    // fragment lane mappings (same as attention kernel, validated)
    const int mm   = lane >> 3;
    const int arow = (mm & 1) * 8 + (lane & 7);   // A-fragment row
    const int acol = (mm >> 1) * 8;               // A-fragment col
    const int brow = (mm >> 1) * 8 + (lane & 7);  // B-fragment row (n)
    const int bcol = (mm & 1) * 8;                // B-fragment col (k)

    float acc[2][8][4];
#pragma unroll
    for (int i = 0; i < 2; i++)
#pragma unroll
        for (int j = 0; j < 8; j++)
#pragma unroll
            for (int r = 0; r < 4; r++) acc[i][j][r] = 0.f;

    const int nch = K / GBK;                 // 64
    load_stage(0, 0);
    load_stage(1, GBK);
    load_stage(2, 2 * GBK);

    for (int ch = 0; ch < nch; ch++) {
        const int s = ch & 3;
        if (ch + 3 < nch) {
            load_stage((ch + 3) & 3, (ch + 3) * GBK);
            CP_WAIT(3);
        } else if (ch + 2 < nch) {
            CP_WAIT(2);
        } else if (ch + 1 < nch) {
            CP_WAIT(1);
        } else {
            CP_WAIT(0);
        }
        __syncthreads();

        const uint32_t As = sb + (uint32_t)s * STAGE_B;
        const uint32_t Bs = As + APLANE_B;

#pragma unroll
        for (int ks = 0; ks < GBK; ks += 16) {
            uint32_t af[2][4];
            ldsm4(af[0], As + ((wm + arow) * GLD + ks + acol) * 2);
            ldsm4(af[1], As + ((wm + 16 + arow) * GLD + ks + acol) * 2);
            uint32_t bf[4][4];
#pragma unroll
            for (int j = 0; j < 4; j++)
                ldsm4(bf[j], Bs + ((wn + j * 16 + brow) * GLD + ks + bcol) * 2);
#pragma unroll
            for (int i = 0; i < 2; i++)
#pragma unroll
                for (int j = 0; j < 4; j++) {
                    mma16816(acc[i][2 * j],     af[i], bf[j]);
                    mma16816(acc[i][2 * j + 1], af[i], bf[j] + 2);
                }
        }
        __syncthreads();
    }

    // Epilogue: lane (r0, c0) owns rows wm+i*16+r0(+8), cols wn+j*8+c0..+1
    const int r0 = lane >> 2;
    const int c0 = (lane & 3) * 2;
#pragma unroll
    for (int i = 0; i < 2; i++) {
        size_t rowa = (size_t)(m0 + wm + i * 16 + r0) * N + n0 + wn + c0;
        size_t rowb = rowa + (size_t)8 * N;
#pragma unroll
        for (int j = 0; j < 8; j++) {
            store2(C + rowa + j * 8, acc[i][j][0], acc[i][j][1]);
            store2(C + rowb + j * 8, acc[i][j][2], acc[i][j][3]);
        }
    }
}

// ---------------------------------------------------------------------------
// Flash attention: fp16 inputs, cp.async double-buffered K/V, register O,
// epilogue writes fp16. 128 threads = 4 warps, BQ=BK=64.
// V is read from the fused qkv buffer (row stride vstr).
// ---------------------------------------------------------------------------
#define KP 136
#define ATILE_H (64 * KP)
#define ATT_SMEM (4 * ATILE_H * 2)

__global__ __launch_bounds__(128, 2) void attn_h(const __half* __restrict__ q,
                                                 const __half* __restrict__ k,
                                                 const __half* __restrict__ v,
                                                 int vstr,
                                                 __half* __restrict__ yh) {
    extern __shared__ __align__(16) __half asm_[];
    __half* KsA[2] = {asm_, asm_ + ATILE_H};
    __half* VsA[2] = {asm_ + 2 * ATILE_H, asm_ + 3 * ATILE_H};

    const int qt = (int)gridDim.x - 1 - (int)blockIdx.x;  // longest first
    const int h  = blockIdx.y;
    const int b  = blockIdx.z;
    const int q0 = qt * 64;
    const int g  = h / RF;

    const int tid  = threadIdx.x;
    const int lane = tid & 31;
    const int warp = tid >> 5;
    const int wrow = warp * 16;

    // Stage Q (pre-scaled in rope_h) into KsA[0].
    for (int i = tid; i < 64 * 16; i += 128) {
        int row = i >> 4, c8 = (i & 15) * 8;
        *(uint4*)(KsA[0] + row * KP + c8) =
            *(const uint4*)(q + ((size_t)(b * TT + q0 + row)) * DD + h * DK + c8);
    }
    __syncthreads();

    const int mm   = lane >> 3;
    const int arow = (mm & 1) * 8 + (lane & 7);
    const int acol = (mm >> 1) * 8;
    const int brow = (mm >> 1) * 8 + (lane & 7);
    const int bcol = (mm & 1) * 8;

    uint32_t Qa[8][4];
#pragma unroll
    for (int kc = 0; kc < 8; kc++)
        ldsm4(Qa[kc], smem_to_u32(KsA[0] + (wrow + arow) * KP + kc * 16 + acol));
    __syncthreads();

    auto load_kv = [&](int kt, int s) {
        uint32_t kb = smem_to_u32(KsA[s]);
        uint32_t vb = smem_to_u32(VsA[s]);
        const __half* kp = k + ((size_t)(b * TT + kt * 64)) * 512 + g * DK;
        const __half* vp = v + ((size_t)(b * TT + kt * 64)) * vstr + g * DK;
        for (int i = tid; i < 1024; i += 128) {
            int row = i >> 4, cb = (i & 15) * 16;
            uint32_t so = (uint32_t)(row * (KP * 2) + cb);
            cp16(kb + so, (const char*)(kp + (size_t)row * 512) + cb);
            cp16(vb + so, (const char*)(vp + (size_t)row * vstr) + cb);
        }
        CP_COMMIT();
    };

    float Ofr[16][4];
#pragma unroll
    for (int nb = 0; nb < 16; nb++)
#pragma unroll
        for (int j = 0; j < 4; j++) Ofr[nb][j] = 0.f;

    float m0r = -1e30f, m1r = -1e30f, l0r = 0.f, l1r = 0.f;
    const int r0 = lane >> 2;
    const int c0 = (lane & 3) * 2;

    load_kv(0, 0);

    for (int kt = 0; kt <= qt; kt++) {
        const int s = kt & 1;
        if (kt < qt) {
            load_kv(kt + 1, s ^ 1);
            CP_WAIT(1);
        } else {
            CP_WAIT(0);
        }
        __syncthreads();
        const __half* Ks = KsA[s];
        const __half* Vs = VsA[s];

        float S[8][4];
#pragma unroll
        for (int nb = 0; nb < 8; nb++)
#pragma unroll
            for (int j = 0; j < 4; j++) S[nb][j] = 0.f;

#pragma unroll
        for (int kc = 0; kc < 8; kc++)
#pragma unroll
            for (int nbp = 0; nbp < 4; nbp++) {
                uint32_t bb[4];
                ldsm4(bb, smem_to_u32(Ks + (nbp * 16 + brow) * KP + kc * 16 + bcol));
                mma16816(S[2 * nbp],     Qa[kc], bb);
                mma16816(S[2 * nbp + 1], Qa[kc], bb + 2);
            }

        if (kt == qt) {
            const int rl0 = wrow + r0, rl1 = rl0 + 8;
#pragma unroll
            for (int nb = 0; nb < 8; nb++) {
                int colb = nb * 8 + c0;
                if (colb     > rl0) S[nb][0] = -1e30f;
                if (colb + 1 > rl0) S[nb][1] = -1e30f;
                if (colb     > rl1) S[nb][2] = -1e30f;
                if (colb + 1 > rl1) S[nb][3] = -1e30f;
            }
        }

        float mx0 = -1e30f, mx1 = -1e30f;
#pragma unroll
        for (int nb = 0; nb < 8; nb++) {
            mx0 = fmaxf(mx0, fmaxf(S[nb][0], S[nb][1]));
            mx1 = fmaxf(mx1, fmaxf(S[nb][2], S[nb][3]));
        }
        mx0 = fmaxf(mx0, __shfl_xor_sync(0xffffffffu, mx0, 1));
        mx0 = fmaxf(mx0, __shfl_xor_sync(0xffffffffu, mx0, 2));
        mx1 = fmaxf(mx1, __shfl_xor_sync(0xffffffffu, mx1, 1));
        mx1 = fmaxf(mx1, __shfl_xor_sync(0xffffffffu, mx1, 2));

        float mn0 = fmaxf(m0r, mx0), mn1 = fmaxf(m1r, mx1);
        float a0 = __expf(m0r - mn0), a1 = __expf(m1r - mn1);
        float s0 = 0.f, s1 = 0.f;
#pragma unroll
        for (int nb = 0; nb < 8; nb++) {
            S[nb][0] = __expf(S[nb][0] - mn0);
            S[nb][1] = __expf(S[nb][1] - mn0);
            S[nb][2] = __expf(S[nb][2] - mn1);
            S[nb][3] = __expf(S[nb][3] - mn1);
            s0 += S[nb][0] + S[nb][1];
            s1 += S[nb][2] + S[nb][3];
        }
        s0 += __shfl_xor_sync(0xffffffffu, s0, 1);
        s0 += __shfl_xor_sync(0xffffffffu, s0, 2);
        s1 += __shfl_xor_sync(0xffffffffu, s1, 1);
        s1 += __shfl_xor_sync(0xffffffffu, s1, 2);
        l0r = l0r * a0 + s0;
        l1r = l1r * a1 + s1;
        m0r = mn0; m1r = mn1;

#pragma unroll
        for (int nb = 0; nb < 16; nb++) {
            Ofr[nb][0] *= a0; Ofr[nb][1] *= a0;
            Ofr[nb][2] *= a1; Ofr[nb][3] *= a1;
        }

        uint32_t Pa[4][4];
#pragma unroll
        for (int kc = 0; kc < 4; kc++) {
            Pa[kc][0] = packh2(S[2 * kc][0],     S[2 * kc][1]);
            Pa[kc][1] = packh2(S[2 * kc][2],     S[2 * kc][3]);
            Pa[kc][2] = packh2(S[2 * kc + 1][0], S[2 * kc + 1][1]);
            Pa[kc][3] = packh2(S[2 * kc + 1][2], S[2 * kc + 1][3]);
        }

#pragma unroll
        for (int kc = 0; kc < 4; kc++)
#pragma unroll
            for (int nbp = 0; nbp < 8; nbp++) {
                uint32_t bb[4];
                ldsm4t(bb, smem_to_u32(Vs + (kc * 16 + arow) * KP + nbp * 16 + acol));
                mma16816(Ofr[2 * nbp],     Pa[kc], bb);
                mma16816(Ofr[2 * nbp + 1], Pa[kc], bb + 2);
            }
        __syncthreads();
    }

    // Epilogue: normalize, write fp16 y.
    const float i0 = 1.f / l0r, i1 = 1.f / l1r;
#pragma unroll
    for (int nb = 0; nb < 16; nb++) {
        size_t base0 = ((size_t)(b * TT + q0 + wrow + r0)) * DD + h * DK + nb * 8 + c0;
        size_t base1 = base0 + (size_t)8 * DD;
        *(__half2*)(yh + base0) = __floats2half2_rn(Ofr[nb][0] * i0, Ofr[nb][1] * i0);
        *(__half2*)(yh + base1) = __floats2half2_rn(Ofr[nb][2] * i1, Ofr[nb][3] * i1);
    }
}

// ---------------------------------------------------------------------------
// Launch
// ---------------------------------------------------------------------------
extern "C" void kernel_launch(void* const* d_in, const int* in_sizes, int n_in,
                              void* d_out, int out_size) {
    const float* x  = (const float*)d_in[0];
    const float* Wq = (const float*)d_in[1];
    const float* Wk = (const float*)d_in[2];
    const float* Wv = (const float*)d_in[3];
    const float* Wo = (const float*)d_in[4];
    float* out = (float*)d_out;

    __half *qkv, *qh, *kh, *xh, *yh, *wt, *wo;
    cudaGetSymbolAddress((void**)&qkv, g_qkv);
    cudaGetSymbolAddress((void**)&qh, g_qh);
    cudaGetSymbolAddress((void**)&kh, g_kh);
    cudaGetSymbolAddress((void**)&xh, g_xh);
    cudaGetSymbolAddress((void**)&yh, g_yh);
    cudaGetSymbolAddress((void**)&wt, g_wt);
    cudaGetSymbolAddress((void**)&wo, g_wo);

    const int M = BB * TT;            // 4096
    const int nx = M * DD;

    // Prep: x -> fp16; transpose weights to fp16 [N,K]
    conv_x<<<(nx + 255) / 256, 256>>>(x, xh, nx);
    transpose_h<<<dim3(DD / 32, DD / 32), dim3(32, 8)>>>(Wq, wt, DD, DD);
    transpose_h<<<dim3(512 / 32, DD / 32), dim3(32, 8)>>>(
        Wk, wt + (size_t)2048 * DD, DD, 512);
    transpose_h<<<dim3(512 / 32, DD / 32), dim3(32, 8)>>>(
        Wv, wt + (size_t)2560 * DD, DD, 512);
    transpose_h<<<dim3(DD / 32, DD / 32), dim3(32, 8)>>>(Wo, wo, DD, DD);

    cudaFuncSetAttribute(gemm_mma<__half>, cudaFuncAttributeMaxDynamicSharedMemorySize, GEMM_SMEM);
    cudaFuncSetAttribute(gemm_mma<float>,  cudaFuncAttributeMaxDynamicSharedMemorySize, GEMM_SMEM);

    // Fused QKV projection (fp16 out)
    gemm_mma<__half><<<dim3(3072 / GBN, M / GBM), 512, GEMM_SMEM>>>(xh, wt, qkv, M, 3072, DD);

    // RoPE -> fp16 (q pre-scaled by 1/sqrt(dk))
    const float rs = 0.08838834764831845f;
    rope_h<<<(M * HH * 64 + 255) / 256, 256>>>(qkv, qh, HH, DD, rs, M * HH * 64);
    rope_h<<<(M * GG * 64 + 255) / 256, 256>>>(qkv + 2048, kh, GG, 512, 1.0f, M * GG * 64);

    // Attention (V read directly from qkv, row stride 3072)
    cudaFuncSetAttribute(attn_h, cudaFuncAttributeMaxDynamicSharedMemorySize, ATT_SMEM);
    attn_h<<<dim3(TT / 64, HH, BB), 128, ATT_SMEM>>>(qh, kh, qkv + 2560, 3072, yh);

    // Output projection (fp32 out)
    gemm_mma<float><<<dim3(DD / GBN, M / GBM), 512, GEMM_SMEM>>>(yh, wo, out, M, DD, DD);
}

// round 10
// speedup vs baseline: 6.8019x; 1.0020x over previous
#include <cuda_runtime.h>
#include <cuda_bf16.h>
#include <cuda_fp16.h>
#include <cstdint>
#include <cstddef>

// Problem constants
#define BB 2
#define TT 2048
#define DD 2048
#define HH 16
#define GG 4
#define DK 128
#define RF (HH / GG)   // 4

// ---------------------------------------------------------------------------
// Scratch (__device__ globals; no allocation allowed)
// ---------------------------------------------------------------------------
__device__ __align__(16) __half g_qkv[(size_t)BB * TT * 3072];     // fused QKV out (fp16)
__device__ __align__(16) __half g_qh[(size_t)BB * TT * DD];
__device__ __align__(16) __half g_kh[(size_t)BB * TT * 512];
__device__ __align__(16) __half g_xh[(size_t)BB * TT * DD];        // x fp16
__device__ __align__(16) __half g_yh[(size_t)BB * TT * DD];        // attn out fp16
__device__ __align__(16) __half g_wt[(size_t)DD * 3072];           // [Wq|Wk|Wv] fp16, K-major
__device__ __align__(16) __half g_wo[(size_t)DD * DD];             // Wo fp16, K-major

// ---------------------------------------------------------------------------
// PTX helpers
// ---------------------------------------------------------------------------
__device__ __forceinline__ void cp16(uint32_t s, const void* g) {
    asm volatile("cp.async.cg.shared.global [%0], [%1], 16;"
                 :: "r"(s), "l"(__cvta_generic_to_global(g)));
}
#define CP_COMMIT() asm volatile("cp.async.commit_group;" ::: "memory")
#define CP_WAIT(n)  asm volatile("cp.async.wait_group %0;" :: "n"(n) : "memory")

__device__ __forceinline__ uint32_t smem_to_u32(const void* p) {
    uint32_t a;
    asm("{ .reg .u64 t; cvta.to.shared.u64 t, %1; cvt.u32.u64 %0, t; }"
        : "=r"(a) : "l"(p));
    return a;
}

__device__ __forceinline__ void mma16816(float* d, const uint32_t* a, const uint32_t* b) {
    asm volatile("mma.sync.aligned.m16n8k16.row.col.f32.f16.f16.f32 "
        "{%0,%1,%2,%3}, {%4,%5,%6,%7}, {%8,%9}, {%0,%1,%2,%3};"
        : "+f"(d[0]), "+f"(d[1]), "+f"(d[2]), "+f"(d[3])
        : "r"(a[0]), "r"(a[1]), "r"(a[2]), "r"(a[3]), "r"(b[0]), "r"(b[1]));
}
__device__ __forceinline__ void ldsm4(uint32_t* r, uint32_t addr) {
    asm volatile("ldmatrix.sync.aligned.m8n8.x4.shared.b16 {%0,%1,%2,%3}, [%4];"
        : "=r"(r[0]), "=r"(r[1]), "=r"(r[2]), "=r"(r[3]) : "r"(addr));
}
__device__ __forceinline__ void ldsm4t(uint32_t* r, uint32_t addr) {
    asm volatile("ldmatrix.sync.aligned.m8n8.x4.trans.shared.b16 {%0,%1,%2,%3}, [%4];"
        : "=r"(r[0]), "=r"(r[1]), "=r"(r[2]), "=r"(r[3]) : "r"(addr));
}
__device__ __forceinline__ uint32_t packh2(float a, float b) {
    __half2 h = __floats2half2_rn(a, b);
    return *(uint32_t*)&h;
}

// typed pair store for GEMM epilogue
__device__ __forceinline__ void store2(__half* p, float a, float b) {
    *(__half2*)p = __floats2half2_rn(a, b);
}
__device__ __forceinline__ void store2(float* p, float a, float b) {
    *(float2*)p = make_float2(a, b);
}

// ---------------------------------------------------------------------------
// Prep kernels (elementwise converts only — no transposes)
// ---------------------------------------------------------------------------
__global__ void conv_x(const float* __restrict__ x, __half* __restrict__ h, int n) {
    int i = blockIdx.x * blockDim.x + threadIdx.x;
    if (i < n) h[i] = __float2half_rn(x[i]);
}

// Fuse Wq|Wk|Wv (all [2048, N_i] K-major) into wt [2048, 3072] fp16
__global__ void conv_w3(const float* __restrict__ Wq, const float* __restrict__ Wk,
                        const float* __restrict__ Wv, __half* __restrict__ o, int n) {
    int i = blockIdx.x * blockDim.x + threadIdx.x;
    if (i >= n) return;
    int k = i / 3072, c = i % 3072;
    float v;
    if (c < 2048)      v = Wq[(size_t)k * 2048 + c];
    else if (c < 2560) v = Wk[(size_t)k * 512 + c - 2048];
    else               v = Wv[(size_t)k * 512 + c - 2560];
    o[i] = __float2half_rn(v);
}

// RoPE from fused qkv (fp16, row stride 3072) -> fp16, optional scale.
__global__ void rope_h(const __half* __restrict__ src, __half* __restrict__ dst,
                       int nh, int ostride, float scale, int total) {
    int idx = blockIdx.x * blockDim.x + threadIdx.x;
    if (idx >= total) return;
    int i  = idx & 63;
    int h  = (idx >> 6) % nh;
    int bt = idx / (64 * nh);
    int t  = bt % TT;

    const float log_theta_over_64 = 0.14391156f;
    float freq = __expf(-(float)i * log_theta_over_64);
    float ang  = (float)t * freq;
    float s, c;
    sincosf(ang, &s, &c);

    size_t sbase = (size_t)bt * 3072 + h * DK;
    float x1 = __half2float(src[sbase + i]);
    float x2 = __half2float(src[sbase + 64 + i]);
    size_t obase = (size_t)bt * ostride + h * DK;
    dst[obase + i]      = __float2half((x1 * c - x2 * s) * scale);
    dst[obase + 64 + i] = __float2half((x2 * c + x1 * s) * scale);
}

// ---------------------------------------------------------------------------
// Raw-mma fp16 GEMM: C[M,N] = A[M,K] @ W[K,N], OutT out.
// A k-major in smem (ldsm), W k-major in smem (ldsm.trans) — no weight
// transpose needed. CTA tile 128x256x32, 512 threads = 16 warps (4m x 4n).
// 4-stage cp.async pipeline.
// ---------------------------------------------------------------------------
#define GBM 128
#define GBN 256
#define GBK 32
#define ALD 40                            // A pitch (halves)
#define BLD 264                           // B pitch (halves): 256 + 8
#define APLANE_B (128 * ALD * 2)          // 10240
#define BPLANE_B (32 * BLD * 2)           // 16896
#define STAGE_B (APLANE_B + BPLANE_B)     // 27136
#define NSTAGE 4
#define GEMM_SMEM (NSTAGE * STAGE_B)      // 108544

template <typename OutT>
__global__ __launch_bounds__(512) void gemm_mma(const __half* __restrict__ A,
                                                const __half* __restrict__ W,
                                                OutT* __restrict__ C,
                                                int M, int N, int K) {
    extern __shared__ __align__(16) char smem[];
    const uint32_t sb = smem_to_u32(smem);
    const int tid  = threadIdx.x;
    const int lane = tid & 31;
    const int warp = tid >> 5;
    const int m0 = blockIdx.y * GBM;
    const int n0 = blockIdx.x * GBN;
    const int wm = (warp & 3) * 32;
    const int wn = (warp >> 2) * 64;

    const __half* Ap = A + (size_t)m0 * K;
    const __half* Wp = W + n0;

    // per stage: A 512 chunks (128 rows x 64B), B 1024 chunks (32 rows x 512B)
    auto load_stage = [&](int s, int kc) {
        uint32_t base = sb + (uint32_t)s * STAGE_B;
#pragma unroll
        for (int it = 0; it < 3; it++) {
            int id = it * 512 + tid;
            if (id < 512) {
                int row = id >> 2, c16 = (id & 3) * 16;
                cp16(base + (uint32_t)row * (ALD * 2) + c16,
                     Ap + (size_t)row * K + kc + (c16 >> 1));
            } else {
                int id2 = id - 512;
                int row = id2 >> 5, c16 = (id2 & 31) * 16;
                cp16(base + APLANE_B + (uint32_t)row * (BLD * 2) + c16,
                     Wp + (size_t)(kc + row) * N + (c16 >> 1));
            }
        }
        CP_COMMIT();
    };

    const int mm   = lane >> 3;
    const int arow = (mm & 1) * 8 + (lane & 7);   // A row / B-k row
    const int acol = (mm >> 1) * 8;               // A col / B-n col

    float acc[2][8][4];
#pragma unroll
    for (int i = 0; i < 2; i++)
#pragma unroll
        for (int j = 0; j < 8; j++)
#pragma unroll
            for (int r = 0; r < 4; r++) acc[i][j][r] = 0.f;

    const int nch = K / GBK;                 // 64
    load_stage(0, 0);
    load_stage(1, GBK);
    load_stage(2, 2 * GBK);

    for (int ch = 0; ch < nch; ch++) {
        const int s = ch & 3;
        if (ch + 3 < nch) {
            load_stage((ch + 3) & 3, (ch + 3) * GBK);
            CP_WAIT(3);
        } else if (ch + 2 < nch) {
            CP_WAIT(2);
        } else if (ch + 1 < nch) {
            CP_WAIT(1);
        } else {
            CP_WAIT(0);
        }
        __syncthreads();

        const uint32_t As = sb + (uint32_t)s * STAGE_B;
        const uint32_t Bs = As + APLANE_B;

#pragma unroll
        for (int ks = 0; ks < GBK; ks += 16) {
            uint32_t af[2][4];
            ldsm4(af[0], As + ((wm + arow) * ALD + ks + acol) * 2);
            ldsm4(af[1], As + ((wm + 16 + arow) * ALD + ks + acol) * 2);
            uint32_t bf[4][4];
#pragma unroll
            for (int j = 0; j < 4; j++)
                ldsm4t(bf[j], Bs + ((ks + arow) * BLD + wn + j * 16 + acol) * 2);
#pragma unroll
            for (int i = 0; i < 2; i++)
#pragma unroll
                for (int j = 0; j < 4; j++) {
                    mma16816(acc[i][2 * j],     af[i], bf[j]);
                    mma16816(acc[i][2 * j + 1], af[i], bf[j] + 2);
                }
        }
        __syncthreads();
    }

    const int r0 = lane >> 2;
    const int c0 = (lane & 3) * 2;
#pragma unroll
    for (int i = 0; i < 2; i++) {
        size_t rowa = (size_t)(m0 + wm + i * 16 + r0) * N + n0 + wn + c0;
        size_t rowb = rowa + (size_t)8 * N;
#pragma unroll
        for (int j = 0; j < 8; j++) {
            store2(C + rowa + j * 8, acc[i][j][0], acc[i][j][1]);
            store2(C + rowb + j * 8, acc[i][j][2], acc[i][j][3]);
        }
    }
}

// ---------------------------------------------------------------------------
// Flash attention: BQ=128, BK=64, 256 threads = 8 warps (16 q-rows each).
// fp16 inputs, cp.async double-buffered K/V, register O, fp16 out.
// V read from fused qkv (row stride vstr).
// ---------------------------------------------------------------------------
#define KP 136
#define ATILE_H (64 * KP)
#define ATT_SMEM (4 * ATILE_H * 2)        // 69632

__global__ __launch_bounds__(256) void attn_h(const __half* __restrict__ q,
                                              const __half* __restrict__ k,
                                              const __half* __restrict__ v,
                                              int vstr,
                                              __half* __restrict__ yh) {
    extern __shared__ __align__(16) __half asm_[];
    __half* KsA[2] = {asm_, asm_ + ATILE_H};
    __half* VsA[2] = {asm_ + 2 * ATILE_H, asm_ + 3 * ATILE_H};

    const int qt = (int)gridDim.x - 1 - (int)blockIdx.x;  // longest first
    const int h  = blockIdx.y;
    const int b  = blockIdx.z;
    const int q0 = qt * 128;
    const int g  = h / RF;

    const int tid  = threadIdx.x;
    const int lane = tid & 31;
    const int warp = tid >> 5;
    const int wrow = warp * 16;

    // Stage Q (128 rows; uses both K buffers as staging before pipeline starts)
    for (int i = tid; i < 128 * 16; i += 256) {
        int row = i >> 4, c8 = (i & 15) * 8;
        *(uint4*)(asm_ + row * KP + c8) =
            *(const uint4*)(q + ((size_t)(b * TT + q0 + row)) * DD + h * DK + c8);
    }
    __syncthreads();

    const int mm   = lane >> 3;
    const int arow = (mm & 1) * 8 + (lane & 7);
    const int acol = (mm >> 1) * 8;
    const int brow = (mm >> 1) * 8 + (lane & 7);
    const int bcol = (mm & 1) * 8;

    uint32_t Qa[8][4];
#pragma unroll
    for (int kc = 0; kc < 8; kc++)
        ldsm4(Qa[kc], smem_to_u32(asm_ + (wrow + arow) * KP + kc * 16 + acol));
    __syncthreads();

    auto load_kv = [&](int kt, int s) {
        uint32_t kb = smem_to_u32(KsA[s]);
        uint32_t vb = smem_to_u32(VsA[s]);
        const __half* kp = k + ((size_t)(b * TT + kt * 64)) * 512 + g * DK;
        const __half* vp = v + ((size_t)(b * TT + kt * 64)) * vstr + g * DK;
        for (int i = tid; i < 1024; i += 256) {
            int row = i >> 4, cb = (i & 15) * 16;
            uint32_t so = (uint32_t)(row * (KP * 2) + cb);
            cp16(kb + so, (const char*)(kp + (size_t)row * 512) + cb);
            cp16(vb + so, (const char*)(vp + (size_t)row * vstr) + cb);
        }
        CP_COMMIT();
    };

    float Ofr[16][4];
#pragma unroll
    for (int nb = 0; nb < 16; nb++)
#pragma unroll
        for (int j = 0; j < 4; j++) Ofr[nb][j] = 0.f;

    float m0r = -1e30f, m1r = -1e30f, l0r = 0.f, l1r = 0.f;
    const int r0 = lane >> 2;
    const int c0 = (lane & 3) * 2;

    const int nkt = 2 * qt + 2;           // causal: tiles 0 .. 2qt+1
    load_kv(0, 0);

    for (int kt = 0; kt < nkt; kt++) {
        const int s = kt & 1;
        if (kt + 1 < nkt) {
            load_kv(kt + 1, s ^ 1);
            CP_WAIT(1);
        } else {
            CP_WAIT(0);
        }
        __syncthreads();
        const int k0 = kt * 64;
        const bool active = (k0 <= q0 + wrow + 15);   // any of this warp's rows unmasked

        if (active) {
            const __half* Ks = KsA[s];
            const __half* Vs = VsA[s];

            float S[8][4];
#pragma unroll
            for (int nb = 0; nb < 8; nb++)
#pragma unroll
                for (int j = 0; j < 4; j++) S[nb][j] = 0.f;

#pragma unroll
            for (int kc = 0; kc < 8; kc++)
#pragma unroll
                for (int nbp = 0; nbp < 4; nbp++) {
                    uint32_t bb[4];
                    ldsm4(bb, smem_to_u32(Ks + (nbp * 16 + brow) * KP + kc * 16 + bcol));
                    mma16816(S[2 * nbp],     Qa[kc], bb);
                    mma16816(S[2 * nbp + 1], Qa[kc], bb + 2);
                }

            if (k0 + 63 > q0 + wrow) {   // diagonal tile for this warp
                const int rl0 = q0 + wrow + r0, rl1 = rl0 + 8;
#pragma unroll
                for (int nb = 0; nb < 8; nb++) {
                    int colb = k0 + nb * 8 + c0;
                    if (colb     > rl0) S[nb][0] = -1e30f;
                    if (colb + 1 > rl0) S[nb][1] = -1e30f;
                    if (colb     > rl1) S[nb][2] = -1e30f;
                    if (colb + 1 > rl1) S[nb][3] = -1e30f;
                }
            }

            float mx0 = -1e30f, mx1 = -1e30f;
#pragma unroll
            for (int nb = 0; nb < 8; nb++) {
                mx0 = fmaxf(mx0, fmaxf(S[nb][0], S[nb][1]));
                mx1 = fmaxf(mx1, fmaxf(S[nb][2], S[nb][3]));
            }
            mx0 = fmaxf(mx0, __shfl_xor_sync(0xffffffffu, mx0, 1));
            mx0 = fmaxf(mx0, __shfl_xor_sync(0xffffffffu, mx0, 2));
            mx1 = fmaxf(mx1, __shfl_xor_sync(0xffffffffu, mx1, 1));
            mx1 = fmaxf(mx1, __shfl_xor_sync(0xffffffffu, mx1, 2));

            float mn0 = fmaxf(m0r, mx0), mn1 = fmaxf(m1r, mx1);
            float a0 = __expf(m0r - mn0), a1 = __expf(m1r - mn1);
            float s0 = 0.f, s1 = 0.f;
#pragma unroll
            for (int nb = 0; nb < 8; nb++) {
                S[nb][0] = __expf(S[nb][0] - mn0);
                S[nb][1] = __expf(S[nb][1] - mn0);
                S[nb][2] = __expf(S[nb][2] - mn1);
                S[nb][3] = __expf(S[nb][3] - mn1);
                s0 += S[nb][0] + S[nb][1];
                s1 += S[nb][2] + S[nb][3];
            }
            s0 += __shfl_xor_sync(0xffffffffu, s0, 1);
            s0 += __shfl_xor_sync(0xffffffffu, s0, 2);
            s1 += __shfl_xor_sync(0xffffffffu, s1, 1);
            s1 += __shfl_xor_sync(0xffffffffu, s1, 2);
            l0r = l0r * a0 + s0;
            l1r = l1r * a1 + s1;
            m0r = mn0; m1r = mn1;

#pragma unroll
            for (int nb = 0; nb < 16; nb++) {
                Ofr[nb][0] *= a0; Ofr[nb][1] *= a0;
                Ofr[nb][2] *= a1; Ofr[nb][3] *= a1;
            }

            uint32_t Pa[4][4];
#pragma unroll
            for (int kc = 0; kc < 4; kc++) {
                Pa[kc][0] = packh2(S[2 * kc][0],     S[2 * kc][1]);
                Pa[kc][1] = packh2(S[2 * kc][2],     S[2 * kc][3]);
                Pa[kc][2] = packh2(S[2 * kc + 1][0], S[2 * kc + 1][1]);
                Pa[kc][3] = packh2(S[2 * kc + 1][2], S[2 * kc + 1][3]);
            }

#pragma unroll
            for (int kc = 0; kc < 4; kc++)
#pragma unroll
                for (int nbp = 0; nbp < 8; nbp++) {
                    uint32_t bb[4];
                    ldsm4t(bb, smem_to_u32(Vs + (kc * 16 + arow) * KP + nbp * 16 + acol));
                    mma16816(Ofr[2 * nbp],     Pa[kc], bb);
                    mma16816(Ofr[2 * nbp + 1], Pa[kc], bb + 2);
                }
        }
        __syncthreads();
    }

    // Epilogue: normalize, write fp16 y.
    const float i0 = 1.f / l0r, i1 = 1.f / l1r;
#pragma unroll
    for (int nb = 0; nb < 16; nb++) {
        size_t base0 = ((size_t)(b * TT + q0 + wrow + r0)) * DD + h * DK + nb * 8 + c0;
        size_t base1 = base0 + (size_t)8 * DD;
        *(__half2*)(yh + base0) = __floats2half2_rn(Ofr[nb][0] * i0, Ofr[nb][1] * i0);
        *(__half2*)(yh + base1) = __floats2half2_rn(Ofr[nb][2] * i1, Ofr[nb][3] * i1);
    }
}

// ---------------------------------------------------------------------------
// Launch
// ---------------------------------------------------------------------------
extern "C" void kernel_launch(void* const* d_in, const int* in_sizes, int n_in,
                              void* d_out, int out_size) {
    const float* x  = (const float*)d_in[0];
    const float* Wq = (const float*)d_in[1];
    const float* Wk = (const float*)d_in[2];
    const float* Wv = (const float*)d_in[3];
    const float* Wo = (const float*)d_in[4];
    float* out = (float*)d_out;

    __half *qkv, *qh, *kh, *xh, *yh, *wt, *wo;
    cudaGetSymbolAddress((void**)&qkv, g_qkv);
    cudaGetSymbolAddress((void**)&qh, g_qh);
    cudaGetSymbolAddress((void**)&kh, g_kh);
    cudaGetSymbolAddress((void**)&xh, g_xh);
    cudaGetSymbolAddress((void**)&yh, g_yh);
    cudaGetSymbolAddress((void**)&wt, g_wt);
    cudaGetSymbolAddress((void**)&wo, g_wo);

    const int M = BB * TT;            // 4096
    const int nx = M * DD;

    // Prep: elementwise converts only
    conv_x<<<(nx + 255) / 256, 256>>>(x, xh, nx);
    conv_w3<<<(DD * 3072 + 255) / 256, 256>>>(Wq, Wk, Wv, wt, DD * 3072);
    conv_x<<<(DD * DD + 255) / 256, 256>>>(Wo, wo, DD * DD);

    cudaFuncSetAttribute(gemm_mma<__half>, cudaFuncAttributeMaxDynamicSharedMemorySize, GEMM_SMEM);
    cudaFuncSetAttribute(gemm_mma<float>,  cudaFuncAttributeMaxDynamicSharedMemorySize, GEMM_SMEM);

    // Fused QKV projection (fp16 out)
    gemm_mma<__half><<<dim3(3072 / GBN, M / GBM), 512, GEMM_SMEM>>>(xh, wt, qkv, M, 3072, DD);

    // RoPE -> fp16 (q pre-scaled by 1/sqrt(dk))
    const float rs = 0.08838834764831845f;
    rope_h<<<(M * HH * 64 + 255) / 256, 256>>>(qkv, qh, HH, DD, rs, M * HH * 64);
    rope_h<<<(M * GG * 64 + 255) / 256, 256>>>(qkv + 2048, kh, GG, 512, 1.0f, M * GG * 64);

    // Attention (BQ=128; V read directly from qkv, row stride 3072)
    cudaFuncSetAttribute(attn_h, cudaFuncAttributeMaxDynamicSharedMemorySize, ATT_SMEM);
    attn_h<<<dim3(TT / 128, HH, BB), 256, ATT_SMEM>>>(qh, kh, qkv + 2560, 3072, yh);

    // Output projection (fp32 out)
    gemm_mma<float><<<dim3(DD / GBN, M / GBM), 512, GEMM_SMEM>>>(yh, wo, out, M, DD, DD);
}